// round 1
// baseline (speedup 1.0000x reference)
#include <cuda_runtime.h>
#include <cuda_bf16.h>
#include <cstdint>

// Problem constants (match reference)
#define NNODES 100000
#define INDIM  256
#define OUTDIM 128

// Scratch: support = X @ W   [NNODES, OUTDIM] fp32 = 51.2 MB
__device__ float g_support[(size_t)NNODES * OUTDIM];

// ---------------------------------------------------------------------------
// Kernel 1: SGEMM  support = X @ W
// Tiling: BM=128, BN=128(=OUTDIM), BK=16, 256 threads, 8x8 micro-tile.
// ---------------------------------------------------------------------------
#define BM 128
#define BN 128
#define BK 16
#define TM 8
#define TN 8

__global__ __launch_bounds__(256) void gemm_kernel(
    const float* __restrict__ x,      // [M, 256]
    const float* __restrict__ w,      // [256, 128]
    float* __restrict__ sup,          // [M, 128]
    int M)
{
    __shared__ float As[BK][BM];      // A transposed in smem for conflict-free reads
    __shared__ float Bs[BK][BN];

    const int tid = threadIdx.x;
    const int block_row = blockIdx.x * BM;

    const int tr = tid / (BN / TN);   // 0..15
    const int tc = tid % (BN / TN);   // 0..15

    float acc[TM][TN];
#pragma unroll
    for (int i = 0; i < TM; i++)
#pragma unroll
        for (int j = 0; j < TN; j++) acc[i][j] = 0.0f;

    for (int k0 = 0; k0 < INDIM; k0 += BK) {
        // Load A tile: BM x BK = 2048 floats = 512 float4; 256 thr -> 2 each
#pragma unroll
        for (int it = 0; it < 2; it++) {
            int i4 = tid + it * 256;          // 0..511
            int r = i4 / (BK / 4);            // row within tile (0..127)
            int c4 = i4 % (BK / 4);           // float4 col (0..3)
            int grow = block_row + r;
            float4 a;
            if (grow < M) {
                a = *reinterpret_cast<const float4*>(x + (size_t)grow * INDIM + k0 + c4 * 4);
            } else {
                a = make_float4(0.f, 0.f, 0.f, 0.f);
            }
            As[c4 * 4 + 0][r] = a.x;
            As[c4 * 4 + 1][r] = a.y;
            As[c4 * 4 + 2][r] = a.z;
            As[c4 * 4 + 3][r] = a.w;
        }
        // Load B tile: BK x BN = 2048 floats = 512 float4
#pragma unroll
        for (int it = 0; it < 2; it++) {
            int i4 = tid + it * 256;
            int r = i4 / (BN / 4);            // 0..15
            int c4 = i4 % (BN / 4);           // 0..31
            float4 b = *reinterpret_cast<const float4*>(w + (size_t)(k0 + r) * OUTDIM + c4 * 4);
            *reinterpret_cast<float4*>(&Bs[r][c4 * 4]) = b;
        }
        __syncthreads();

#pragma unroll
        for (int kk = 0; kk < BK; kk++) {
            float ra[TM], rb[TN];
#pragma unroll
            for (int i = 0; i < TM; i++) ra[i] = As[kk][tr * TM + i];
#pragma unroll
            for (int j = 0; j < TN; j++) rb[j] = Bs[kk][tc * TN + j];
#pragma unroll
            for (int i = 0; i < TM; i++)
#pragma unroll
                for (int j = 0; j < TN; j++)
                    acc[i][j] = fmaf(ra[i], rb[j], acc[i][j]);
        }
        __syncthreads();
    }

    // Write out
#pragma unroll
    for (int i = 0; i < TM; i++) {
        int grow = block_row + tr * TM + i;
        if (grow < M) {
#pragma unroll
            for (int j = 0; j < TN; j += 4) {
                float4 v = make_float4(acc[i][j], acc[i][j + 1], acc[i][j + 2], acc[i][j + 3]);
                *reinterpret_cast<float4*>(sup + (size_t)grow * OUTDIM + tc * TN + j) = v;
            }
        }
    }
}

// ---------------------------------------------------------------------------
// Kernel 2: out[i, :] = bias[:]
// ---------------------------------------------------------------------------
__global__ void init_out_kernel(float* __restrict__ out, const float* __restrict__ bias, int total4)
{
    // bias broadcast via float4; total4 = M*OUTDIM/4
    __shared__ float4 sb[OUTDIM / 4];
    if (threadIdx.x < OUTDIM / 4)
        sb[threadIdx.x] = reinterpret_cast<const float4*>(bias)[threadIdx.x];
    __syncthreads();
    int idx = blockIdx.x * blockDim.x + threadIdx.x;
    int stride = gridDim.x * blockDim.x;
    for (int i = idx; i < total4; i += stride) {
        reinterpret_cast<float4*>(out)[i] = sb[i & (OUTDIM / 4 - 1)];
    }
}

// ---------------------------------------------------------------------------
// Kernel 3: scatter  out[src[e]] += val[e] * support[dst[e]]
// One warp per edge; each lane handles a float4 (32 lanes x 4 = 128 cols).
// ---------------------------------------------------------------------------
__global__ __launch_bounds__(256) void scatter_kernel(
    const float* __restrict__ sup,
    const int* __restrict__ esrc,
    const int* __restrict__ edst,
    const float* __restrict__ eval_,
    float* __restrict__ out,
    int E)
{
    int gwarp = (blockIdx.x * blockDim.x + threadIdx.x) >> 5;
    int lane = threadIdx.x & 31;
    if (gwarp >= E) return;

    int s = esrc[gwarp];
    int d = edst[gwarp];
    float v = eval_[gwarp];

    float4 a = reinterpret_cast<const float4*>(sup + (size_t)d * OUTDIM)[lane];
    float* orow = out + (size_t)s * OUTDIM + lane * 4;
    atomicAdd(orow + 0, v * a.x);
    atomicAdd(orow + 1, v * a.y);
    atomicAdd(orow + 2, v * a.z);
    atomicAdd(orow + 3, v * a.w);
}

// ---------------------------------------------------------------------------
// Launch
// Inputs: x [N*256] f32, weight [256*128] f32, bias [128] f32,
//         edge_src [E] i32, edge_dst [E] i32, edge_val [E] f32
// ---------------------------------------------------------------------------
extern "C" void kernel_launch(void* const* d_in, const int* in_sizes, int n_in,
                              void* d_out, int out_size)
{
    const float* x    = (const float*)d_in[0];
    const float* w    = (const float*)d_in[1];
    const float* bias = (const float*)d_in[2];
    const int*   esrc = (const int*)d_in[3];
    const int*   edst = (const int*)d_in[4];
    const float* ev   = (const float*)d_in[5];
    float* out = (float*)d_out;

    const int M = in_sizes[0] / INDIM;   // 100000
    const int E = in_sizes[3];           // 1600000

    float* sup = nullptr;
    cudaGetSymbolAddress((void**)&sup, g_support);

    // GEMM
    int gblocks = (M + BM - 1) / BM;
    gemm_kernel<<<gblocks, 256>>>(x, w, sup, M);

    // Init output with bias (independent of GEMM)
    int total4 = M * OUTDIM / 4;
    init_out_kernel<<<2048, 256>>>(out, bias, total4);

    // Scatter (8 warps / block)
    int warps_per_block = 256 / 32;
    int sblocks = (E + warps_per_block - 1) / warps_per_block;
    scatter_kernel<<<sblocks, 256>>>(sup, esrc, edst, ev, out, E);
}

// round 2
// speedup vs baseline: 1.3805x; 1.3805x over previous
#include <cuda_runtime.h>
#include <cuda_bf16.h>
#include <cstdint>

// Problem constants (match reference)
#define NNODES 100000
#define INDIM  256
#define OUTDIM 128

// Scratch: support = X @ W   [NNODES, OUTDIM] fp32 = 51.2 MB
__device__ float g_support[(size_t)NNODES * OUTDIM];

// ---------------------------------------------------------------------------
// Kernel 1: SGEMM  support = X @ W   using packed fma.rn.f32x2 (Blackwell)
// Tiling: BM=128, BN=128(=OUTDIM), BK=16, 256 threads, 8x8 micro-tile.
// A is stored DUPLICATED in smem (each value twice, adjacent) so the
// broadcast operand of the packed FMA loads directly as a 64-bit pair.
// ---------------------------------------------------------------------------
#define BM 128
#define BN 128
#define BK 16
#define TM 8
#define TN 8

__global__ __launch_bounds__(256) void gemm_kernel(
    const float* __restrict__ x,      // [M, 256]
    const float* __restrict__ w,      // [256, 128]
    float* __restrict__ sup,          // [M, 128]
    int M)
{
    __shared__ float As2[BK][2 * BM]; // duplicated-pair layout: [k][2r]=[k][2r+1]=A[r][k]
    __shared__ float Bs[BK][BN];

    const int tid = threadIdx.x;
    const int block_row = blockIdx.x * BM;

    const int tr = tid / (BN / TN);   // 0..15
    const int tc = tid % (BN / TN);   // 0..15

    // 32 packed accumulators (64 regs), each holds 2 adjacent N columns
    unsigned long long acc2[TM][TN / 2];
#pragma unroll
    for (int i = 0; i < TM; i++)
#pragma unroll
        for (int j = 0; j < TN / 2; j++) acc2[i][j] = 0ULL;

    for (int k0 = 0; k0 < INDIM; k0 += BK) {
        // Load A tile: BM x BK = 2048 floats = 512 float4; 256 thr -> 2 each
#pragma unroll
        for (int it = 0; it < 2; it++) {
            int i4 = tid + it * 256;          // 0..511
            int r = i4 / (BK / 4);            // row within tile (0..127)
            int c4 = i4 % (BK / 4);           // float4 col (0..3)
            int grow = block_row + r;
            float4 a;
            if (grow < M) {
                a = *reinterpret_cast<const float4*>(x + (size_t)grow * INDIM + k0 + c4 * 4);
            } else {
                a = make_float4(0.f, 0.f, 0.f, 0.f);
            }
            As2[c4 * 4 + 0][2 * r] = a.x;  As2[c4 * 4 + 0][2 * r + 1] = a.x;
            As2[c4 * 4 + 1][2 * r] = a.y;  As2[c4 * 4 + 1][2 * r + 1] = a.y;
            As2[c4 * 4 + 2][2 * r] = a.z;  As2[c4 * 4 + 2][2 * r + 1] = a.z;
            As2[c4 * 4 + 3][2 * r] = a.w;  As2[c4 * 4 + 3][2 * r + 1] = a.w;
        }
        // Load B tile: BK x BN = 2048 floats = 512 float4
#pragma unroll
        for (int it = 0; it < 2; it++) {
            int i4 = tid + it * 256;
            int r = i4 / (BN / 4);            // 0..15
            int c4 = i4 % (BN / 4);           // 0..31
            float4 b = *reinterpret_cast<const float4*>(w + (size_t)(k0 + r) * OUTDIM + c4 * 4);
            *reinterpret_cast<float4*>(&Bs[r][c4 * 4]) = b;
        }
        __syncthreads();

#pragma unroll
        for (int kk = 0; kk < BK; kk++) {
            // ra2[i] = {A[r_i][k], A[r_i][k]} packed; loaded as LDS.128 (2 pairs per load)
            unsigned long long ra2[TM], rb2[TN / 2];
            const ulonglong2* rap =
                reinterpret_cast<const ulonglong2*>(&As2[kk][2 * (tr * TM)]);
#pragma unroll
            for (int p = 0; p < TM / 2; p++) {
                ulonglong2 v = rap[p];
                ra2[2 * p + 0] = v.x;
                ra2[2 * p + 1] = v.y;
            }
            const ulonglong2* rbp =
                reinterpret_cast<const ulonglong2*>(&Bs[kk][tc * TN]);
#pragma unroll
            for (int p = 0; p < TN / 4; p++) {
                ulonglong2 v = rbp[p];
                rb2[2 * p + 0] = v.x;
                rb2[2 * p + 1] = v.y;
            }
#pragma unroll
            for (int i = 0; i < TM; i++)
#pragma unroll
                for (int j = 0; j < TN / 2; j++)
                    asm("fma.rn.f32x2 %0, %1, %2, %0;"
                        : "+l"(acc2[i][j])
                        : "l"(ra2[i]), "l"(rb2[j]));
        }
        __syncthreads();
    }

    // Write out: unpack pairs
#pragma unroll
    for (int i = 0; i < TM; i++) {
        int grow = block_row + tr * TM + i;
        if (grow < M) {
            float outv[TN];
#pragma unroll
            for (int j = 0; j < TN / 2; j++) {
                float lo, hi;
                asm("mov.b64 {%0, %1}, %2;" : "=f"(lo), "=f"(hi) : "l"(acc2[i][j]));
                outv[2 * j + 0] = lo;
                outv[2 * j + 1] = hi;
            }
#pragma unroll
            for (int j = 0; j < TN; j += 4) {
                float4 v = make_float4(outv[j], outv[j + 1], outv[j + 2], outv[j + 3]);
                *reinterpret_cast<float4*>(sup + (size_t)grow * OUTDIM + tc * TN + j) = v;
            }
        }
    }
}

// ---------------------------------------------------------------------------
// Kernel 2: out[i, :] = bias[:]
// ---------------------------------------------------------------------------
__global__ void init_out_kernel(float* __restrict__ out, const float* __restrict__ bias, int total4)
{
    __shared__ float4 sb[OUTDIM / 4];
    if (threadIdx.x < OUTDIM / 4)
        sb[threadIdx.x] = reinterpret_cast<const float4*>(bias)[threadIdx.x];
    __syncthreads();
    int idx = blockIdx.x * blockDim.x + threadIdx.x;
    int stride = gridDim.x * blockDim.x;
    for (int i = idx; i < total4; i += stride) {
        reinterpret_cast<float4*>(out)[i] = sb[i & (OUTDIM / 4 - 1)];
    }
}

// ---------------------------------------------------------------------------
// Kernel 3: scatter  out[src[e]] += val[e] * support[dst[e]]
// One warp per edge; each lane handles a float4 (32 lanes x 4 = 128 cols).
// Uses red.global.add.v4.f32 (sm_90a+) — one 16B vector reduction per lane
// instead of 4 scalar atomics.
// ---------------------------------------------------------------------------
__global__ __launch_bounds__(256) void scatter_kernel(
    const float* __restrict__ sup,
    const int* __restrict__ esrc,
    const int* __restrict__ edst,
    const float* __restrict__ eval_,
    float* __restrict__ out,
    int E)
{
    int gwarp = (blockIdx.x * blockDim.x + threadIdx.x) >> 5;
    int lane = threadIdx.x & 31;
    if (gwarp >= E) return;

    int s = esrc[gwarp];
    int d = edst[gwarp];
    float v = eval_[gwarp];

    float4 a = reinterpret_cast<const float4*>(sup + (size_t)d * OUTDIM)[lane];
    float* orow = out + (size_t)s * OUTDIM + lane * 4;
    asm volatile("red.global.add.v4.f32 [%0], {%1, %2, %3, %4};"
                 :: "l"(orow), "f"(v * a.x), "f"(v * a.y), "f"(v * a.z), "f"(v * a.w)
                 : "memory");
}

// ---------------------------------------------------------------------------
// Launch
// Inputs: x [N*256] f32, weight [256*128] f32, bias [128] f32,
//         edge_src [E] i32, edge_dst [E] i32, edge_val [E] f32
// ---------------------------------------------------------------------------
extern "C" void kernel_launch(void* const* d_in, const int* in_sizes, int n_in,
                              void* d_out, int out_size)
{
    const float* x    = (const float*)d_in[0];
    const float* w    = (const float*)d_in[1];
    const float* bias = (const float*)d_in[2];
    const int*   esrc = (const int*)d_in[3];
    const int*   edst = (const int*)d_in[4];
    const float* ev   = (const float*)d_in[5];
    float* out = (float*)d_out;

    const int M = in_sizes[0] / INDIM;   // 100000
    const int E = in_sizes[3];           // 1600000

    float* sup = nullptr;
    cudaGetSymbolAddress((void**)&sup, g_support);

    // GEMM
    int gblocks = (M + BM - 1) / BM;
    gemm_kernel<<<gblocks, 256>>>(x, w, sup, M);

    // Init output with bias
    int total4 = M * OUTDIM / 4;
    init_out_kernel<<<2048, 256>>>(out, bias, total4);

    // Scatter (8 warps / block)
    int warps_per_block = 256 / 32;
    int sblocks = (E + warps_per_block - 1) / warps_per_block;
    scatter_kernel<<<sblocks, 256>>>(sup, esrc, edst, ev, out, E);
}

// round 4
// speedup vs baseline: 1.7471x; 1.2655x over previous
#include <cuda_runtime.h>
#include <cuda_bf16.h>
#include <cstdint>

#define NNODES 100000
#define INDIM  256
#define OUTDIM 128

// Scratch: support = X @ W   [NNODES, OUTDIM] fp32 = 51.2 MB
__device__ float g_support[(size_t)NNODES * OUTDIM];

// ============================================================================
// Helpers
// ============================================================================
__device__ __forceinline__ uint32_t smem_u32(const void* p) {
    uint32_t a;
    asm("{ .reg .u64 t; cvta.to.shared.u64 t, %1; cvt.u32.u64 %0, t; }" : "=r"(a) : "l"(p));
    return a;
}
#define SW128(off) ((off) ^ (((off) >> 3) & 0x70))

__device__ __forceinline__ void ldsm_x4(uint32_t& r0, uint32_t& r1, uint32_t& r2, uint32_t& r3,
                                        uint32_t addr) {
    asm volatile("ldmatrix.sync.aligned.m8n8.x4.shared.b16 {%0, %1, %2, %3}, [%4];"
                 : "=r"(r0), "=r"(r1), "=r"(r2), "=r"(r3) : "r"(addr));
}

__device__ __forceinline__ void mma_bf16(float* c, const uint32_t* a, const uint32_t* b) {
    asm volatile(
        "mma.sync.aligned.m16n8k16.row.col.f32.bf16.bf16.f32 "
        "{%0, %1, %2, %3}, {%4, %5, %6, %7}, {%8, %9}, {%0, %1, %2, %3};"
        : "+f"(c[0]), "+f"(c[1]), "+f"(c[2]), "+f"(c[3])
        : "r"(a[0]), "r"(a[1]), "r"(a[2]), "r"(a[3]), "r"(b[0]), "r"(b[1]));
}

// ============================================================================
// GEMM: support = X @ W via bf16 split-precision mma.sync (HMMA tensor path)
//   support = x_hi@w_hi + x_hi@w_lo + x_lo@w_hi  (fp32 accumulate)
// CTA tile 128x128, 8 warps (4x2), warp tile 32x64, K chunk 64.
// SMEM per chunk: A_hi/A_lo [128m][64k] bf16 SW128 (16KB each),
//                 B_hi/B_lo [128n][64k] bf16 SW128 (16KB each) = 64KB total.
// ============================================================================
#define SM_AHI 0
#define SM_ALO 16384
#define SM_BHI 32768
#define SM_BLO 49152
#define SM_GEMM_TOTAL 65536

__global__ __launch_bounds__(256) void gemm_mma_kernel(
    const float* __restrict__ x,      // [M, 256]
    const float* __restrict__ w,      // [256, 128]
    float* __restrict__ sup,          // [M, 128]
    int M)
{
    extern __shared__ char smem[];
    const uint32_t sbase = smem_u32(smem);
    const int tid = threadIdx.x;
    const int wid = tid >> 5;
    const int lane = tid & 31;
    const int block_row = blockIdx.x * 128;

    const int m_off = (wid & 3) * 32;   // warp m offset within CTA tile
    const int n_off = (wid >> 2) * 64;  // warp n offset

    // Accumulators: 2 m16-tiles x 8 n8-tiles x 4 floats = 64 regs
    float acc[2][8][4];
#pragma unroll
    for (int mt = 0; mt < 2; mt++)
#pragma unroll
        for (int nt = 0; nt < 8; nt++)
#pragma unroll
            for (int q = 0; q < 4; q++) acc[mt][nt][q] = 0.0f;

    // ldmatrix per-lane address components (shared by A and B tiles):
    // row_in_16tile = lane & 15, k half (8 cols) = lane >> 4
    const int lrow = lane & 15;
    const int lkh = (lane >> 4) * 8;

    for (int kc = 0; kc < 4; kc++) {
        if (kc > 0) __syncthreads();   // previous chunk fully consumed

        // ---- Fill A chunk: 128 rows x 64 k fp32 -> bf16 hi/lo, SW128
        {
            int r = tid >> 1;
            int half = tid & 1;
            int grow = block_row + r;
            const float4* src = reinterpret_cast<const float4*>(
                x + (size_t)grow * INDIM + kc * 64 + half * 32);
#pragma unroll
            for (int q = 0; q < 8; q++) {
                float4 f = (grow < M) ? src[q] : make_float4(0.f, 0.f, 0.f, 0.f);
                int c0 = half * 32 + q * 4;
                __nv_bfloat16 hx = __float2bfloat16(f.x);
                __nv_bfloat16 hy = __float2bfloat16(f.y);
                __nv_bfloat16 hz = __float2bfloat16(f.z);
                __nv_bfloat16 hw = __float2bfloat16(f.w);
                __nv_bfloat162 ph0 = __nv_bfloat162(hx, hy);
                __nv_bfloat162 ph1 = __nv_bfloat162(hz, hw);
                __nv_bfloat162 pl0 = __nv_bfloat162(
                    __float2bfloat16(f.x - __bfloat162float(hx)),
                    __float2bfloat16(f.y - __bfloat162float(hy)));
                __nv_bfloat162 pl1 = __nv_bfloat162(
                    __float2bfloat16(f.z - __bfloat162float(hz)),
                    __float2bfloat16(f.w - __bfloat162float(hw)));
                uint32_t boff = (uint32_t)r * 128 + (uint32_t)c0 * 2;
                uint32_t sw0 = SW128(boff);
                uint32_t sw1 = SW128(boff + 4);
                *reinterpret_cast<__nv_bfloat162*>(smem + SM_AHI + sw0) = ph0;
                *reinterpret_cast<__nv_bfloat162*>(smem + SM_AHI + sw1) = ph1;
                *reinterpret_cast<__nv_bfloat162*>(smem + SM_ALO + sw0) = pl0;
                *reinterpret_cast<__nv_bfloat162*>(smem + SM_ALO + sw1) = pl1;
            }
        }
        // ---- Fill B chunk: stored [n][k] (k contiguous), n=0..127, kk=0..63
        {
            int n = tid & 127;
            int kg = (tid >> 7) * 32;
#pragma unroll 8
            for (int kk = kg; kk < kg + 32; kk++) {
                float f = w[(size_t)(kc * 64 + kk) * OUTDIM + n];
                __nv_bfloat16 h = __float2bfloat16(f);
                __nv_bfloat16 l = __float2bfloat16(f - __bfloat162float(h));
                uint32_t boff = (uint32_t)n * 128 + (uint32_t)kk * 2;
                uint32_t sw = SW128(boff);
                *reinterpret_cast<__nv_bfloat16*>(smem + SM_BHI + sw) = h;
                *reinterpret_cast<__nv_bfloat16*>(smem + SM_BLO + sw) = l;
            }
        }
        __syncthreads();

        // ---- MMA over this chunk: 4 k16-steps x 3 precision terms
#pragma unroll
        for (int ks = 0; ks < 4; ks++) {
            const int k_off = ks * 16;
            // lane-specific swizzled byte offset within a [*, 64] bf16 tile,
            // for a 16-row tile starting at tile_row:
            //   off(tile_row) = SW128((tile_row + lrow)*128 + (k_off + lkh)*2)
            uint32_t a_addr[2], b_addr[4];
#pragma unroll
            for (int mt = 0; mt < 2; mt++) {
                uint32_t boff = (uint32_t)(m_off + mt * 16 + lrow) * 128 +
                                (uint32_t)(k_off + lkh) * 2;
                a_addr[mt] = sbase + SW128(boff);
            }
#pragma unroll
            for (int np = 0; np < 4; np++) {
                uint32_t boff = (uint32_t)(n_off + np * 16 + lrow) * 128 +
                                (uint32_t)(k_off + lkh) * 2;
                b_addr[np] = sbase + SW128(boff);
            }

            uint32_t a_hi[2][4], a_lo[2][4], b[4][4];

            // B_hi fragments
#pragma unroll
            for (int np = 0; np < 4; np++)
                ldsm_x4(b[np][0], b[np][1], b[np][2], b[np][3], b_addr[np] + SM_BHI);
            // A_hi fragments
#pragma unroll
            for (int mt = 0; mt < 2; mt++)
                ldsm_x4(a_hi[mt][0], a_hi[mt][1], a_hi[mt][2], a_hi[mt][3],
                        a_addr[mt] + SM_AHI);
            // hh term
#pragma unroll
            for (int mt = 0; mt < 2; mt++)
#pragma unroll
                for (int np = 0; np < 4; np++) {
                    uint32_t b0[2] = { b[np][0], b[np][2] };   // n-tile 2*np
                    uint32_t b1[2] = { b[np][1], b[np][3] };   // n-tile 2*np+1
                    mma_bf16(acc[mt][2 * np + 0], a_hi[mt], b0);
                    mma_bf16(acc[mt][2 * np + 1], a_hi[mt], b1);
                }
            // A_lo fragments -> lh term (a_lo x b_hi)
#pragma unroll
            for (int mt = 0; mt < 2; mt++)
                ldsm_x4(a_lo[mt][0], a_lo[mt][1], a_lo[mt][2], a_lo[mt][3],
                        a_addr[mt] + SM_ALO);
#pragma unroll
            for (int mt = 0; mt < 2; mt++)
#pragma unroll
                for (int np = 0; np < 4; np++) {
                    uint32_t b0[2] = { b[np][0], b[np][2] };
                    uint32_t b1[2] = { b[np][1], b[np][3] };
                    mma_bf16(acc[mt][2 * np + 0], a_lo[mt], b0);
                    mma_bf16(acc[mt][2 * np + 1], a_lo[mt], b1);
                }
            // B_lo fragments (reuse b regs) -> hl term (a_hi x b_lo)
#pragma unroll
            for (int np = 0; np < 4; np++)
                ldsm_x4(b[np][0], b[np][1], b[np][2], b[np][3], b_addr[np] + SM_BLO);
#pragma unroll
            for (int mt = 0; mt < 2; mt++)
#pragma unroll
                for (int np = 0; np < 4; np++) {
                    uint32_t b0[2] = { b[np][0], b[np][2] };
                    uint32_t b1[2] = { b[np][1], b[np][3] };
                    mma_bf16(acc[mt][2 * np + 0], a_hi[mt], b0);
                    mma_bf16(acc[mt][2 * np + 1], a_hi[mt], b1);
                }
        }
    }

    // ---- Epilogue: thread owns rows (m_off + mt*16 + lane/4) and (+8),
    // cols n_off + nt*8 + 2*(lane%3..) per mma fragment spec.
    const int rbase = block_row + m_off + (lane >> 2);
    const int cbase = n_off + 2 * (lane & 3);
#pragma unroll
    for (int mt = 0; mt < 2; mt++) {
        int r0 = rbase + mt * 16;
        int r1 = r0 + 8;
        if (r0 < M) {
            float* d0 = sup + (size_t)r0 * OUTDIM + cbase;
#pragma unroll
            for (int nt = 0; nt < 8; nt++)
                *reinterpret_cast<float2*>(d0 + nt * 8) =
                    make_float2(acc[mt][nt][0], acc[mt][nt][1]);
        }
        if (r1 < M) {
            float* d1 = sup + (size_t)r1 * OUTDIM + cbase;
#pragma unroll
            for (int nt = 0; nt < 8; nt++)
                *reinterpret_cast<float2*>(d1 + nt * 8) =
                    make_float2(acc[mt][nt][2], acc[mt][nt][3]);
        }
    }
}

// ---------------------------------------------------------------------------
// Kernel 2: out[i, :] = bias[:]
// ---------------------------------------------------------------------------
__global__ void init_out_kernel(float* __restrict__ out, const float* __restrict__ bias, int total4)
{
    __shared__ float4 sb[OUTDIM / 4];
    if (threadIdx.x < OUTDIM / 4)
        sb[threadIdx.x] = reinterpret_cast<const float4*>(bias)[threadIdx.x];
    __syncthreads();
    int idx = blockIdx.x * blockDim.x + threadIdx.x;
    int stride = gridDim.x * blockDim.x;
    for (int i = idx; i < total4; i += stride) {
        reinterpret_cast<float4*>(out)[i] = sb[i & (OUTDIM / 4 - 1)];
    }
}

// ---------------------------------------------------------------------------
// Kernel 3: scatter  out[src[e]] += val[e] * support[dst[e]]
// One warp per edge; lane handles a float4; red.global.add.v4.f32.
// ---------------------------------------------------------------------------
__global__ __launch_bounds__(256) void scatter_kernel(
    const float* __restrict__ sup,
    const int* __restrict__ esrc,
    const int* __restrict__ edst,
    const float* __restrict__ eval_,
    float* __restrict__ out,
    int E)
{
    int gwarp = (blockIdx.x * blockDim.x + threadIdx.x) >> 5;
    int lane = threadIdx.x & 31;
    if (gwarp >= E) return;

    int s = esrc[gwarp];
    int d = edst[gwarp];
    float v = eval_[gwarp];

    float4 a = reinterpret_cast<const float4*>(sup + (size_t)d * OUTDIM)[lane];
    float* orow = out + (size_t)s * OUTDIM + lane * 4;
    asm volatile("red.global.add.v4.f32 [%0], {%1, %2, %3, %4};"
                 :: "l"(orow), "f"(v * a.x), "f"(v * a.y), "f"(v * a.z), "f"(v * a.w)
                 : "memory");
}

// ---------------------------------------------------------------------------
extern "C" void kernel_launch(void* const* d_in, const int* in_sizes, int n_in,
                              void* d_out, int out_size)
{
    const float* x    = (const float*)d_in[0];
    const float* w    = (const float*)d_in[1];
    const float* bias = (const float*)d_in[2];
    const int*   esrc = (const int*)d_in[3];
    const int*   edst = (const int*)d_in[4];
    const float* ev   = (const float*)d_in[5];
    float* out = (float*)d_out;

    const int M = in_sizes[0] / INDIM;   // 100000
    const int E = in_sizes[3];           // 1600000

    float* sup = nullptr;
    cudaGetSymbolAddress((void**)&sup, g_support);

    cudaFuncSetAttribute(gemm_mma_kernel,
                         cudaFuncAttributeMaxDynamicSharedMemorySize, SM_GEMM_TOTAL);

    // GEMM (tensor cores via mma.sync)
    int gblocks = (M + 127) / 128;
    gemm_mma_kernel<<<gblocks, 256, SM_GEMM_TOTAL>>>(x, w, sup, M);

    // Init output with bias
    int total4 = M * OUTDIM / 4;
    init_out_kernel<<<2048, 256>>>(out, bias, total4);

    // Scatter (8 warps / block)
    int sblocks = (E + 7) / 8;
    scatter_kernel<<<sblocks, 256>>>(sup, esrc, edst, ev, out, E);
}

// round 5
// speedup vs baseline: 1.9990x; 1.1442x over previous
#include <cuda_runtime.h>
#include <cuda_bf16.h>
#include <cstdint>

#define NNODES 100000
#define INDIM  256
#define OUTDIM 128

// Scratch
__device__ float g_support[(size_t)NNODES * OUTDIM];                 // 51.2 MB
__device__ __align__(16) __nv_bfloat16 g_wh[INDIM * OUTDIM];         // 64 KB, [kc][n][kk]
__device__ __align__(16) __nv_bfloat16 g_wl[INDIM * OUTDIM];         // 64 KB

// ============================================================================
// Helpers
// ============================================================================
__device__ __forceinline__ uint32_t smem_u32(const void* p) {
    uint32_t a;
    asm("{ .reg .u64 t; cvta.to.shared.u64 t, %1; cvt.u32.u64 %0, t; }" : "=r"(a) : "l"(p));
    return a;
}
#define SW128(off) ((off) ^ (((off) >> 3) & 0x70))

__device__ __forceinline__ void ldsm_x4(uint32_t& r0, uint32_t& r1, uint32_t& r2, uint32_t& r3,
                                        uint32_t addr) {
    asm volatile("ldmatrix.sync.aligned.m8n8.x4.shared.b16 {%0, %1, %2, %3}, [%4];"
                 : "=r"(r0), "=r"(r1), "=r"(r2), "=r"(r3) : "r"(addr));
}

__device__ __forceinline__ void mma_bf16(float* c, const uint32_t* a, const uint32_t* b) {
    asm volatile(
        "mma.sync.aligned.m16n8k16.row.col.f32.bf16.bf16.f32 "
        "{%0, %1, %2, %3}, {%4, %5, %6, %7}, {%8, %9}, {%0, %1, %2, %3};"
        : "+f"(c[0]), "+f"(c[1]), "+f"(c[2]), "+f"(c[3])
        : "r"(a[0]), "r"(a[1]), "r"(a[2]), "r"(a[3]), "r"(b[0]), "r"(b[1]));
}

__device__ __forceinline__ void cp_async16(uint32_t smem_dst, const void* gsrc) {
    asm volatile("cp.async.cg.shared.global [%0], [%1], 16;"
                 :: "r"(smem_dst), "l"(gsrc) : "memory");
}
#define CP_COMMIT() asm volatile("cp.async.commit_group;" ::: "memory")
#define CP_WAIT0()  asm volatile("cp.async.wait_group 0;" ::: "memory")

// ============================================================================
// Kernel 0: convert W -> bf16 hi/lo in chunk-major layout [kc][n][kk]
//   (kc = k/64, n = 0..127, kk = k%64)
// ============================================================================
__global__ void wconv_kernel(const float* __restrict__ w,
                             __nv_bfloat16* __restrict__ wh,
                             __nv_bfloat16* __restrict__ wl)
{
    int idx = blockIdx.x * blockDim.x + threadIdx.x;
    if (idx >= INDIM * OUTDIM) return;
    int kc = idx >> 13;           // /8192
    int n  = (idx >> 6) & 127;
    int kk = idx & 63;
    float f = w[(size_t)(kc * 64 + kk) * OUTDIM + n];
    __nv_bfloat16 h = __float2bfloat16(f);
    wh[idx] = h;
    wl[idx] = __float2bfloat16(f - __bfloat162float(h));
}

// ============================================================================
// GEMM: support = X @ W, bf16 split-precision HMMA, software-pipelined.
// CTA tile 128x128, 8 warps (4m x 2n), warp tile 32x64, K chunks of 64.
// SMEM: B hi (4 chunk tiles, 64KB) | B lo (64KB) | A bufs 2 x (hi16K+lo16K)
// ============================================================================
#define SM_BHI  0
#define SM_BLO  65536
#define SM_ABUF 131072          // buf b at SM_ABUF + b*32768; lo at +16384
#define SM_GEMM_TOTAL 196608

__global__ __launch_bounds__(256) void gemm_mma_kernel(
    const float* __restrict__ x,
    const __nv_bfloat16* __restrict__ wh,
    const __nv_bfloat16* __restrict__ wl,
    float* __restrict__ sup,
    int M)
{
    extern __shared__ char smem[];
    const uint32_t sbase = smem_u32(smem);
    const int tid = threadIdx.x;
    const int wid = tid >> 5;
    const int lane = tid & 31;
    const int block_row = blockIdx.x * 128;

    const int m_off = (wid & 3) * 32;
    const int n_off = (wid >> 2) * 64;

    // ---- Issue B cp.async (whole 128KB, one group) ----
    {
        const char* whb = reinterpret_cast<const char*>(wh);
        const char* wlb = reinterpret_cast<const char*>(wl);
#pragma unroll
        for (int i = 0; i < 32; i++) {
            int p = tid + i * 256;                 // 0..8191 16B pieces
            int kc = p >> 10;
            int within = (p & 1023) * 16;          // byte offset in 16KB tile
            uint32_t dst = SW128((uint32_t)within) + kc * 16384;
            cp_async16(sbase + SM_BHI + dst, whb + (size_t)p * 16);
            cp_async16(sbase + SM_BLO + dst, wlb + (size_t)p * 16);
        }
        CP_COMMIT();
    }

    // A staging: thread owns row r = tid>>1, half = tid&1 (32 cols)
    const int ar = tid >> 1;
    const int ahalf = tid & 1;
    const int agrow = block_row + ar;
    const float4* asrc_base = reinterpret_cast<const float4*>(
        x + (size_t)agrow * INDIM + ahalf * 32);

    float4 a4[8];
    // Prefetch chunk 0
#pragma unroll
    for (int q = 0; q < 8; q++)
        a4[q] = (agrow < M) ? asrc_base[q] : make_float4(0.f, 0.f, 0.f, 0.f);

    // Convert+STS lambda-ish macro body (chunk regs -> buf)
    auto convert_sts = [&](int buf) {
        uint32_t hibase = (uint32_t)SM_ABUF + (uint32_t)buf * 32768;
#pragma unroll
        for (int q = 0; q < 8; q++) {
            float4 f = a4[q];
            int c0 = ahalf * 32 + q * 4;
            __nv_bfloat16 hx = __float2bfloat16(f.x);
            __nv_bfloat16 hy = __float2bfloat16(f.y);
            __nv_bfloat16 hz = __float2bfloat16(f.z);
            __nv_bfloat16 hw = __float2bfloat16(f.w);
            __nv_bfloat162 ph0 = __nv_bfloat162(hx, hy);
            __nv_bfloat162 ph1 = __nv_bfloat162(hz, hw);
            __nv_bfloat162 pl0 = __nv_bfloat162(
                __float2bfloat16(f.x - __bfloat162float(hx)),
                __float2bfloat16(f.y - __bfloat162float(hy)));
            __nv_bfloat162 pl1 = __nv_bfloat162(
                __float2bfloat16(f.z - __bfloat162float(hz)),
                __float2bfloat16(f.w - __bfloat162float(hw)));
            uint32_t boff = (uint32_t)ar * 128 + (uint32_t)c0 * 2;
            uint32_t sw0 = SW128(boff);
            uint32_t sw1 = SW128(boff + 4);
            *reinterpret_cast<__nv_bfloat162*>(smem + hibase + sw0) = ph0;
            *reinterpret_cast<__nv_bfloat162*>(smem + hibase + sw1) = ph1;
            *reinterpret_cast<__nv_bfloat162*>(smem + hibase + 16384 + sw0) = pl0;
            *reinterpret_cast<__nv_bfloat162*>(smem + hibase + 16384 + sw1) = pl1;
        }
    };

    convert_sts(0);
    CP_WAIT0();              // B resident
    __syncthreads();         // buf0 + B visible

    // Accumulators
    float acc[2][8][4];
#pragma unroll
    for (int mt = 0; mt < 2; mt++)
#pragma unroll
        for (int nt = 0; nt < 8; nt++)
#pragma unroll
            for (int q = 0; q < 4; q++) acc[mt][nt][q] = 0.0f;

    const int lrow = lane & 15;
    const int lkh = (lane >> 4) * 8;

    for (int kc = 0; kc < 4; kc++) {
        // Prefetch next A chunk into regs (latency hidden under MMAs)
        if (kc < 3) {
#pragma unroll
            for (int q = 0; q < 8; q++)
                a4[q] = (agrow < M) ? asrc_base[(kc + 1) * 16 + q]
                                    : make_float4(0.f, 0.f, 0.f, 0.f);
        }

        const uint32_t abuf_hi = sbase + SM_ABUF + (uint32_t)(kc & 1) * 32768;
        const uint32_t bchunk = (uint32_t)kc * 16384;

#pragma unroll
        for (int ks = 0; ks < 4; ks++) {
            const int k_off = ks * 16;
            uint32_t a_addr[2], b_addr[4];
#pragma unroll
            for (int mt = 0; mt < 2; mt++) {
                uint32_t boff = (uint32_t)(m_off + mt * 16 + lrow) * 128 +
                                (uint32_t)(k_off + lkh) * 2;
                a_addr[mt] = abuf_hi + SW128(boff);
            }
#pragma unroll
            for (int np = 0; np < 4; np++) {
                uint32_t boff = (uint32_t)(n_off + np * 16 + lrow) * 128 +
                                (uint32_t)(k_off + lkh) * 2;
                b_addr[np] = sbase + bchunk + SW128(boff);
            }

            uint32_t a_hi[2][4], a_lo[2][4], b[4][4];

#pragma unroll
            for (int np = 0; np < 4; np++)
                ldsm_x4(b[np][0], b[np][1], b[np][2], b[np][3], b_addr[np] + SM_BHI);
#pragma unroll
            for (int mt = 0; mt < 2; mt++)
                ldsm_x4(a_hi[mt][0], a_hi[mt][1], a_hi[mt][2], a_hi[mt][3], a_addr[mt]);
#pragma unroll
            for (int mt = 0; mt < 2; mt++)
#pragma unroll
                for (int np = 0; np < 4; np++) {
                    uint32_t b0[2] = { b[np][0], b[np][2] };
                    uint32_t b1[2] = { b[np][1], b[np][3] };
                    mma_bf16(acc[mt][2 * np + 0], a_hi[mt], b0);
                    mma_bf16(acc[mt][2 * np + 1], a_hi[mt], b1);
                }
#pragma unroll
            for (int mt = 0; mt < 2; mt++)
                ldsm_x4(a_lo[mt][0], a_lo[mt][1], a_lo[mt][2], a_lo[mt][3],
                        a_addr[mt] + 16384);
#pragma unroll
            for (int mt = 0; mt < 2; mt++)
#pragma unroll
                for (int np = 0; np < 4; np++) {
                    uint32_t b0[2] = { b[np][0], b[np][2] };
                    uint32_t b1[2] = { b[np][1], b[np][3] };
                    mma_bf16(acc[mt][2 * np + 0], a_lo[mt], b0);
                    mma_bf16(acc[mt][2 * np + 1], a_lo[mt], b1);
                }
#pragma unroll
            for (int np = 0; np < 4; np++)
                ldsm_x4(b[np][0], b[np][1], b[np][2], b[np][3], b_addr[np] + SM_BLO);
#pragma unroll
            for (int mt = 0; mt < 2; mt++)
#pragma unroll
                for (int np = 0; np < 4; np++) {
                    uint32_t b0[2] = { b[np][0], b[np][2] };
                    uint32_t b1[2] = { b[np][1], b[np][3] };
                    mma_bf16(acc[mt][2 * np + 0], a_hi[mt], b0);
                    mma_bf16(acc[mt][2 * np + 1], a_hi[mt], b1);
                }
        }

        // Convert + store next chunk into the other buffer, then sync
        if (kc < 3) {
            convert_sts((kc + 1) & 1);
            __syncthreads();
        }
    }

    // ---- Epilogue ----
    const int rbase = block_row + m_off + (lane >> 2);
    const int cbase = n_off + 2 * (lane & 3);
#pragma unroll
    for (int mt = 0; mt < 2; mt++) {
        int r0 = rbase + mt * 16;
        int r1 = r0 + 8;
        if (r0 < M) {
            float* d0 = sup + (size_t)r0 * OUTDIM + cbase;
#pragma unroll
            for (int nt = 0; nt < 8; nt++)
                *reinterpret_cast<float2*>(d0 + nt * 8) =
                    make_float2(acc[mt][nt][0], acc[mt][nt][1]);
        }
        if (r1 < M) {
            float* d1 = sup + (size_t)r1 * OUTDIM + cbase;
#pragma unroll
            for (int nt = 0; nt < 8; nt++)
                *reinterpret_cast<float2*>(d1 + nt * 8) =
                    make_float2(acc[mt][nt][2], acc[mt][nt][3]);
        }
    }
}

// ---------------------------------------------------------------------------
// Kernel 2: out[i, :] = bias[:]
// ---------------------------------------------------------------------------
__global__ void init_out_kernel(float* __restrict__ out, const float* __restrict__ bias, int total4)
{
    __shared__ float4 sb[OUTDIM / 4];
    if (threadIdx.x < OUTDIM / 4)
        sb[threadIdx.x] = reinterpret_cast<const float4*>(bias)[threadIdx.x];
    __syncthreads();
    int idx = blockIdx.x * blockDim.x + threadIdx.x;
    int stride = gridDim.x * blockDim.x;
    for (int i = idx; i < total4; i += stride) {
        reinterpret_cast<float4*>(out)[i] = sb[i & (OUTDIM / 4 - 1)];
    }
}

// ---------------------------------------------------------------------------
// Kernel 3: scatter  out[src[e]] += val[e] * support[dst[e]]
// ---------------------------------------------------------------------------
__global__ __launch_bounds__(256) void scatter_kernel(
    const float* __restrict__ sup,
    const int* __restrict__ esrc,
    const int* __restrict__ edst,
    const float* __restrict__ eval_,
    float* __restrict__ out,
    int E)
{
    int gwarp = (blockIdx.x * blockDim.x + threadIdx.x) >> 5;
    int lane = threadIdx.x & 31;
    if (gwarp >= E) return;

    int s = esrc[gwarp];
    int d = edst[gwarp];
    float v = eval_[gwarp];

    float4 a = reinterpret_cast<const float4*>(sup + (size_t)d * OUTDIM)[lane];
    float* orow = out + (size_t)s * OUTDIM + lane * 4;
    asm volatile("red.global.add.v4.f32 [%0], {%1, %2, %3, %4};"
                 :: "l"(orow), "f"(v * a.x), "f"(v * a.y), "f"(v * a.z), "f"(v * a.w)
                 : "memory");
}

// ---------------------------------------------------------------------------
extern "C" void kernel_launch(void* const* d_in, const int* in_sizes, int n_in,
                              void* d_out, int out_size)
{
    const float* x    = (const float*)d_in[0];
    const float* w    = (const float*)d_in[1];
    const float* bias = (const float*)d_in[2];
    const int*   esrc = (const int*)d_in[3];
    const int*   edst = (const int*)d_in[4];
    const float* ev   = (const float*)d_in[5];
    float* out = (float*)d_out;

    const int M = in_sizes[0] / INDIM;   // 100000
    const int E = in_sizes[3];           // 1600000

    float* sup = nullptr;
    cudaGetSymbolAddress((void**)&sup, g_support);
    __nv_bfloat16* wh = nullptr;
    cudaGetSymbolAddress((void**)&wh, g_wh);
    __nv_bfloat16* wl = nullptr;
    cudaGetSymbolAddress((void**)&wl, g_wl);

    cudaFuncSetAttribute(gemm_mma_kernel,
                         cudaFuncAttributeMaxDynamicSharedMemorySize, SM_GEMM_TOTAL);

    // Prep: W -> bf16 hi/lo chunked
    wconv_kernel<<<(INDIM * OUTDIM + 255) / 256, 256>>>(w, wh, wl);

    // GEMM
    int gblocks = (M + 127) / 128;
    gemm_mma_kernel<<<gblocks, 256, SM_GEMM_TOTAL>>>(x, wh, wl, sup, M);

    // Init output with bias
    int total4 = M * OUTDIM / 4;
    init_out_kernel<<<2048, 256>>>(out, bias, total4);

    // Scatter
    int sblocks = (E + 7) / 8;
    scatter_kernel<<<sblocks, 256>>>(sup, esrc, edst, ev, out, E);
}

// round 6
// speedup vs baseline: 2.8389x; 1.4201x over previous
#include <cuda_runtime.h>
#include <cuda_bf16.h>
#include <cstdint>

#define NNODES 100000
#define INDIM  256
#define OUTDIM 128
#define NEDGES_MAX 1700000
#define SCAN_BLK 1024
#define NSCAN_BLOCKS ((NNODES + SCAN_BLK - 1) / SCAN_BLK)   // 98

// Scratch
__device__ float g_support[(size_t)NNODES * OUTDIM];                 // 51.2 MB
__device__ __align__(16) __nv_bfloat16 g_wh[INDIM * OUTDIM];
__device__ __align__(16) __nv_bfloat16 g_wl[INDIM * OUTDIM];
__device__ int  g_deg[NNODES];
__device__ int  g_rowtmp[NNODES];
__device__ int  g_rowstart[NNODES];
__device__ int  g_cursor[NNODES];
__device__ int  g_bsum[128];
__device__ int2 g_edges[NEDGES_MAX];                                 // {dst, val bits}

// ============================================================================
// Helpers
// ============================================================================
__device__ __forceinline__ uint32_t smem_u32(const void* p) {
    uint32_t a;
    asm("{ .reg .u64 t; cvta.to.shared.u64 t, %1; cvt.u32.u64 %0, t; }" : "=r"(a) : "l"(p));
    return a;
}
#define SW128(off) ((off) ^ (((off) >> 3) & 0x70))

__device__ __forceinline__ void ldsm_x4(uint32_t& r0, uint32_t& r1, uint32_t& r2, uint32_t& r3,
                                        uint32_t addr) {
    asm volatile("ldmatrix.sync.aligned.m8n8.x4.shared.b16 {%0, %1, %2, %3}, [%4];"
                 : "=r"(r0), "=r"(r1), "=r"(r2), "=r"(r3) : "r"(addr));
}
__device__ __forceinline__ void mma_bf16(float* c, const uint32_t* a, const uint32_t* b) {
    asm volatile(
        "mma.sync.aligned.m16n8k16.row.col.f32.bf16.bf16.f32 "
        "{%0, %1, %2, %3}, {%4, %5, %6, %7}, {%8, %9}, {%0, %1, %2, %3};"
        : "+f"(c[0]), "+f"(c[1]), "+f"(c[2]), "+f"(c[3])
        : "r"(a[0]), "r"(a[1]), "r"(a[2]), "r"(a[3]), "r"(b[0]), "r"(b[1]));
}
__device__ __forceinline__ void cp_async16(uint32_t smem_dst, const void* gsrc) {
    asm volatile("cp.async.cg.shared.global [%0], [%1], 16;"
                 :: "r"(smem_dst), "l"(gsrc) : "memory");
}
#define CP_COMMIT() asm volatile("cp.async.commit_group;" ::: "memory")
#define CP_WAIT0()  asm volatile("cp.async.wait_group 0;" ::: "memory")

// ============================================================================
// Kernel 0: convert W -> bf16 hi/lo in chunk-major layout [kc][n][kk]
// ============================================================================
__global__ void wconv_kernel(const float* __restrict__ w,
                             __nv_bfloat16* __restrict__ wh,
                             __nv_bfloat16* __restrict__ wl)
{
    int idx = blockIdx.x * blockDim.x + threadIdx.x;
    if (idx >= INDIM * OUTDIM) return;
    int kc = idx >> 13;
    int n  = (idx >> 6) & 127;
    int kk = idx & 63;
    float f = w[(size_t)(kc * 64 + kk) * OUTDIM + n];
    __nv_bfloat16 h = __float2bfloat16(f);
    wh[idx] = h;
    wl[idx] = __float2bfloat16(f - __bfloat162float(h));
}

// ============================================================================
// CSR build
// ============================================================================
__global__ void zero_deg_kernel(int* __restrict__ deg, int n)
{
    int i = blockIdx.x * blockDim.x + threadIdx.x;
    if (i < n) deg[i] = 0;
}

__global__ void hist_kernel(const int* __restrict__ esrc, int* __restrict__ deg, int E)
{
    int i = blockIdx.x * blockDim.x + threadIdx.x;
    if (i < E) atomicAdd(&deg[esrc[i]], 1);
}

// Scan pass A: per-block inclusive->exclusive scan of 1024 degrees.
__global__ __launch_bounds__(SCAN_BLK) void scan_a_kernel(
    const int* __restrict__ deg, int* __restrict__ rowtmp, int* __restrict__ bsum, int n)
{
    __shared__ int s[SCAN_BLK];
    int gi = blockIdx.x * SCAN_BLK + threadIdx.x;
    int v = (gi < n) ? deg[gi] : 0;
    s[threadIdx.x] = v;
    __syncthreads();
    // Hillis-Steele inclusive scan
#pragma unroll
    for (int off = 1; off < SCAN_BLK; off <<= 1) {
        int add = (threadIdx.x >= off) ? s[threadIdx.x - off] : 0;
        __syncthreads();
        s[threadIdx.x] += add;
        __syncthreads();
    }
    if (gi < n) rowtmp[gi] = s[threadIdx.x] - v;     // exclusive
    if (threadIdx.x == SCAN_BLK - 1) bsum[blockIdx.x] = s[threadIdx.x];
}

// Scan pass B: exclusive scan of NSCAN_BLOCKS block sums (single block).
__global__ __launch_bounds__(128) void scan_b_kernel(int* __restrict__ bsum, int nb)
{
    __shared__ int s[128];
    int v = (threadIdx.x < nb) ? bsum[threadIdx.x] : 0;
    s[threadIdx.x] = v;
    __syncthreads();
#pragma unroll
    for (int off = 1; off < 128; off <<= 1) {
        int add = (threadIdx.x >= off) ? s[threadIdx.x - off] : 0;
        __syncthreads();
        s[threadIdx.x] += add;
        __syncthreads();
    }
    if (threadIdx.x < nb) bsum[threadIdx.x] = s[threadIdx.x] - v;  // exclusive
}

// Scan pass C: rowstart = rowtmp + bsum[block]; cursor = rowstart.
__global__ void scan_c_kernel(const int* __restrict__ rowtmp, const int* __restrict__ bsum,
                              int* __restrict__ rowstart, int* __restrict__ cursor, int n)
{
    int gi = blockIdx.x * SCAN_BLK + threadIdx.x;
    if (gi < n) {
        int v = rowtmp[gi] + bsum[blockIdx.x];
        rowstart[gi] = v;
        cursor[gi] = v;
    }
}

// Reorder edges into CSR slots: g_edges[pos] = {dst, val}
__global__ void reorder_kernel(const int* __restrict__ esrc, const int* __restrict__ edst,
                               const float* __restrict__ ev, int* __restrict__ cursor,
                               int2* __restrict__ edges, int E)
{
    int i = blockIdx.x * blockDim.x + threadIdx.x;
    if (i >= E) return;
    int s = esrc[i];
    int pos = atomicAdd(&cursor[s], 1);
    edges[pos] = make_int2(edst[i], __float_as_int(ev[i]));
}

// ============================================================================
// Gather: one warp per node. out[node] = bias + sum_e val_e * support[dst_e]
// ============================================================================
__global__ __launch_bounds__(256) void gather_kernel(
    const float* __restrict__ sup,
    const int* __restrict__ rowstart,
    const int* __restrict__ deg,
    const int2* __restrict__ edges,
    const float* __restrict__ bias,
    float* __restrict__ out,
    int N)
{
    int node = (blockIdx.x * blockDim.x + threadIdx.x) >> 5;
    int lane = threadIdx.x & 31;
    if (node >= N) return;

    int start = rowstart[node];
    int d = deg[node];

    float4 acc = reinterpret_cast<const float4*>(bias)[lane];

    for (int c = 0; c < d; c += 32) {
        int nchunk = min(32, d - c);
        int2 p = (lane < nchunk) ? edges[start + c + lane] : make_int2(0, 0);
        for (int j = 0; j < nchunk; j++) {
            int dn  = __shfl_sync(0xFFFFFFFFu, p.x, j);
            float v = __int_as_float(__shfl_sync(0xFFFFFFFFu, p.y, j));
            float4 a = reinterpret_cast<const float4*>(sup + (size_t)dn * OUTDIM)[lane];
            acc.x = fmaf(v, a.x, acc.x);
            acc.y = fmaf(v, a.y, acc.y);
            acc.z = fmaf(v, a.z, acc.z);
            acc.w = fmaf(v, a.w, acc.w);
        }
    }
    reinterpret_cast<float4*>(out + (size_t)node * OUTDIM)[lane] = acc;
}

// ============================================================================
// GEMM (unchanged from R5 winner): bf16 split-precision HMMA, pipelined.
// ============================================================================
#define SM_BHI  0
#define SM_BLO  65536
#define SM_ABUF 131072
#define SM_GEMM_TOTAL 196608

__global__ __launch_bounds__(256) void gemm_mma_kernel(
    const float* __restrict__ x,
    const __nv_bfloat16* __restrict__ wh,
    const __nv_bfloat16* __restrict__ wl,
    float* __restrict__ sup,
    int M)
{
    extern __shared__ char smem[];
    const uint32_t sbase = smem_u32(smem);
    const int tid = threadIdx.x;
    const int wid = tid >> 5;
    const int lane = tid & 31;
    const int block_row = blockIdx.x * 128;

    const int m_off = (wid & 3) * 32;
    const int n_off = (wid >> 2) * 64;

    {
        const char* whb = reinterpret_cast<const char*>(wh);
        const char* wlb = reinterpret_cast<const char*>(wl);
#pragma unroll
        for (int i = 0; i < 32; i++) {
            int p = tid + i * 256;
            int kc = p >> 10;
            int within = (p & 1023) * 16;
            uint32_t dst = SW128((uint32_t)within) + kc * 16384;
            cp_async16(sbase + SM_BHI + dst, whb + (size_t)p * 16);
            cp_async16(sbase + SM_BLO + dst, wlb + (size_t)p * 16);
        }
        CP_COMMIT();
    }

    const int ar = tid >> 1;
    const int ahalf = tid & 1;
    const int agrow = block_row + ar;
    const float4* asrc_base = reinterpret_cast<const float4*>(
        x + (size_t)agrow * INDIM + ahalf * 32);

    float4 a4[8];
#pragma unroll
    for (int q = 0; q < 8; q++)
        a4[q] = (agrow < M) ? asrc_base[q] : make_float4(0.f, 0.f, 0.f, 0.f);

    auto convert_sts = [&](int buf) {
        uint32_t hibase = (uint32_t)SM_ABUF + (uint32_t)buf * 32768;
#pragma unroll
        for (int q = 0; q < 8; q++) {
            float4 f = a4[q];
            int c0 = ahalf * 32 + q * 4;
            __nv_bfloat16 hx = __float2bfloat16(f.x);
            __nv_bfloat16 hy = __float2bfloat16(f.y);
            __nv_bfloat16 hz = __float2bfloat16(f.z);
            __nv_bfloat16 hw = __float2bfloat16(f.w);
            __nv_bfloat162 ph0 = __nv_bfloat162(hx, hy);
            __nv_bfloat162 ph1 = __nv_bfloat162(hz, hw);
            __nv_bfloat162 pl0 = __nv_bfloat162(
                __float2bfloat16(f.x - __bfloat162float(hx)),
                __float2bfloat16(f.y - __bfloat162float(hy)));
            __nv_bfloat162 pl1 = __nv_bfloat162(
                __float2bfloat16(f.z - __bfloat162float(hz)),
                __float2bfloat16(f.w - __bfloat162float(hw)));
            uint32_t boff = (uint32_t)ar * 128 + (uint32_t)c0 * 2;
            uint32_t sw0 = SW128(boff);
            uint32_t sw1 = SW128(boff + 4);
            *reinterpret_cast<__nv_bfloat162*>(smem + hibase + sw0) = ph0;
            *reinterpret_cast<__nv_bfloat162*>(smem + hibase + sw1) = ph1;
            *reinterpret_cast<__nv_bfloat162*>(smem + hibase + 16384 + sw0) = pl0;
            *reinterpret_cast<__nv_bfloat162*>(smem + hibase + 16384 + sw1) = pl1;
        }
    };

    convert_sts(0);
    CP_WAIT0();
    __syncthreads();

    float acc[2][8][4];
#pragma unroll
    for (int mt = 0; mt < 2; mt++)
#pragma unroll
        for (int nt = 0; nt < 8; nt++)
#pragma unroll
            for (int q = 0; q < 4; q++) acc[mt][nt][q] = 0.0f;

    const int lrow = lane & 15;
    const int lkh = (lane >> 4) * 8;

    for (int kc = 0; kc < 4; kc++) {
        if (kc < 3) {
#pragma unroll
            for (int q = 0; q < 8; q++)
                a4[q] = (agrow < M) ? asrc_base[(kc + 1) * 16 + q]
                                    : make_float4(0.f, 0.f, 0.f, 0.f);
        }

        const uint32_t abuf_hi = sbase + SM_ABUF + (uint32_t)(kc & 1) * 32768;
        const uint32_t bchunk = (uint32_t)kc * 16384;

#pragma unroll
        for (int ks = 0; ks < 4; ks++) {
            const int k_off = ks * 16;
            uint32_t a_addr[2], b_addr[4];
#pragma unroll
            for (int mt = 0; mt < 2; mt++) {
                uint32_t boff = (uint32_t)(m_off + mt * 16 + lrow) * 128 +
                                (uint32_t)(k_off + lkh) * 2;
                a_addr[mt] = abuf_hi + SW128(boff);
            }
#pragma unroll
            for (int np = 0; np < 4; np++) {
                uint32_t boff = (uint32_t)(n_off + np * 16 + lrow) * 128 +
                                (uint32_t)(k_off + lkh) * 2;
                b_addr[np] = sbase + bchunk + SW128(boff);
            }

            uint32_t a_hi[2][4], a_lo[2][4], b[4][4];

#pragma unroll
            for (int np = 0; np < 4; np++)
                ldsm_x4(b[np][0], b[np][1], b[np][2], b[np][3], b_addr[np] + SM_BHI);
#pragma unroll
            for (int mt = 0; mt < 2; mt++)
                ldsm_x4(a_hi[mt][0], a_hi[mt][1], a_hi[mt][2], a_hi[mt][3], a_addr[mt]);
#pragma unroll
            for (int mt = 0; mt < 2; mt++)
#pragma unroll
                for (int np = 0; np < 4; np++) {
                    uint32_t b0[2] = { b[np][0], b[np][2] };
                    uint32_t b1[2] = { b[np][1], b[np][3] };
                    mma_bf16(acc[mt][2 * np + 0], a_hi[mt], b0);
                    mma_bf16(acc[mt][2 * np + 1], a_hi[mt], b1);
                }
#pragma unroll
            for (int mt = 0; mt < 2; mt++)
                ldsm_x4(a_lo[mt][0], a_lo[mt][1], a_lo[mt][2], a_lo[mt][3],
                        a_addr[mt] + 16384);
#pragma unroll
            for (int mt = 0; mt < 2; mt++)
#pragma unroll
                for (int np = 0; np < 4; np++) {
                    uint32_t b0[2] = { b[np][0], b[np][2] };
                    uint32_t b1[2] = { b[np][1], b[np][3] };
                    mma_bf16(acc[mt][2 * np + 0], a_lo[mt], b0);
                    mma_bf16(acc[mt][2 * np + 1], a_lo[mt], b1);
                }
#pragma unroll
            for (int np = 0; np < 4; np++)
                ldsm_x4(b[np][0], b[np][1], b[np][2], b[np][3], b_addr[np] + SM_BLO);
#pragma unroll
            for (int mt = 0; mt < 2; mt++)
#pragma unroll
                for (int np = 0; np < 4; np++) {
                    uint32_t b0[2] = { b[np][0], b[np][2] };
                    uint32_t b1[2] = { b[np][1], b[np][3] };
                    mma_bf16(acc[mt][2 * np + 0], a_hi[mt], b0);
                    mma_bf16(acc[mt][2 * np + 1], a_hi[mt], b1);
                }
        }

        if (kc < 3) {
            convert_sts((kc + 1) & 1);
            __syncthreads();
        }
    }

    const int rbase = block_row + m_off + (lane >> 2);
    const int cbase = n_off + 2 * (lane & 3);
#pragma unroll
    for (int mt = 0; mt < 2; mt++) {
        int r0 = rbase + mt * 16;
        int r1 = r0 + 8;
        if (r0 < M) {
            float* d0 = sup + (size_t)r0 * OUTDIM + cbase;
#pragma unroll
            for (int nt = 0; nt < 8; nt++)
                *reinterpret_cast<float2*>(d0 + nt * 8) =
                    make_float2(acc[mt][nt][0], acc[mt][nt][1]);
        }
        if (r1 < M) {
            float* d1 = sup + (size_t)r1 * OUTDIM + cbase;
#pragma unroll
            for (int nt = 0; nt < 8; nt++)
                *reinterpret_cast<float2*>(d1 + nt * 8) =
                    make_float2(acc[mt][nt][2], acc[mt][nt][3]);
        }
    }
}

// ---------------------------------------------------------------------------
extern "C" void kernel_launch(void* const* d_in, const int* in_sizes, int n_in,
                              void* d_out, int out_size)
{
    const float* x    = (const float*)d_in[0];
    const float* w    = (const float*)d_in[1];
    const float* bias = (const float*)d_in[2];
    const int*   esrc = (const int*)d_in[3];
    const int*   edst = (const int*)d_in[4];
    const float* ev   = (const float*)d_in[5];
    float* out = (float*)d_out;

    const int M = in_sizes[0] / INDIM;   // 100000
    const int E = in_sizes[3];           // 1600000

    float* sup;        cudaGetSymbolAddress((void**)&sup, g_support);
    __nv_bfloat16* wh; cudaGetSymbolAddress((void**)&wh, g_wh);
    __nv_bfloat16* wl; cudaGetSymbolAddress((void**)&wl, g_wl);
    int* deg;          cudaGetSymbolAddress((void**)&deg, g_deg);
    int* rowtmp;       cudaGetSymbolAddress((void**)&rowtmp, g_rowtmp);
    int* rowstart;     cudaGetSymbolAddress((void**)&rowstart, g_rowstart);
    int* cursor;       cudaGetSymbolAddress((void**)&cursor, g_cursor);
    int* bsum;         cudaGetSymbolAddress((void**)&bsum, g_bsum);
    int2* edges;       cudaGetSymbolAddress((void**)&edges, g_edges);

    cudaFuncSetAttribute(gemm_mma_kernel,
                         cudaFuncAttributeMaxDynamicSharedMemorySize, SM_GEMM_TOTAL);

    // --- CSR build ---
    zero_deg_kernel<<<(M + 255) / 256, 256>>>(deg, M);
    hist_kernel<<<(E + 255) / 256, 256>>>(esrc, deg, E);
    int nsb = (M + SCAN_BLK - 1) / SCAN_BLK;
    scan_a_kernel<<<nsb, SCAN_BLK>>>(deg, rowtmp, bsum, M);
    scan_b_kernel<<<1, 128>>>(bsum, nsb);
    scan_c_kernel<<<nsb, SCAN_BLK>>>(rowtmp, bsum, rowstart, cursor, M);
    reorder_kernel<<<(E + 255) / 256, 256>>>(esrc, edst, ev, cursor, edges, E);

    // --- GEMM ---
    wconv_kernel<<<(INDIM * OUTDIM + 255) / 256, 256>>>(w, wh, wl);
    int gblocks = (M + 127) / 128;
    gemm_mma_kernel<<<gblocks, 256, SM_GEMM_TOTAL>>>(x, wh, wl, sup, M);

    // --- Gather (fuses bias) ---
    int gth_blocks = (M * 32 + 255) / 256;
    gather_kernel<<<gth_blocks, 256>>>(sup, rowstart, deg, edges, bias, out, M);
}

// round 7
// speedup vs baseline: 3.0526x; 1.0753x over previous
#include <cuda_runtime.h>
#include <cuda_bf16.h>
#include <cstdint>

#define NNODES 100000
#define INDIM  256
#define OUTDIM 128
#define NEDGES_MAX 1700000
#define SCAN_BLK 1024

// Scratch
__device__ float g_support[(size_t)NNODES * OUTDIM];                 // 51.2 MB
__device__ __align__(16) __nv_bfloat16 g_wh[INDIM * OUTDIM];
__device__ __align__(16) __nv_bfloat16 g_wl[INDIM * OUTDIM];
__device__ int  g_deg[NNODES];
__device__ int  g_rowtmp[NNODES];
__device__ int  g_rowstart[NNODES];
__device__ int  g_cursor[NNODES];
__device__ int  g_bsum[128];
__device__ int2 g_edges[NEDGES_MAX];                                 // {dst, val bits}

// ============================================================================
// Helpers
// ============================================================================
__device__ __forceinline__ uint32_t smem_u32(const void* p) {
    uint32_t a;
    asm("{ .reg .u64 t; cvta.to.shared.u64 t, %1; cvt.u32.u64 %0, t; }" : "=r"(a) : "l"(p));
    return a;
}
#define SW128(off) ((off) ^ (((off) >> 3) & 0x70))

__device__ __forceinline__ void ldsm_x4(uint32_t& r0, uint32_t& r1, uint32_t& r2, uint32_t& r3,
                                        uint32_t addr) {
    asm volatile("ldmatrix.sync.aligned.m8n8.x4.shared.b16 {%0, %1, %2, %3}, [%4];"
                 : "=r"(r0), "=r"(r1), "=r"(r2), "=r"(r3) : "r"(addr));
}
__device__ __forceinline__ void mma_bf16(float* c, const uint32_t* a, const uint32_t* b) {
    asm volatile(
        "mma.sync.aligned.m16n8k16.row.col.f32.bf16.bf16.f32 "
        "{%0, %1, %2, %3}, {%4, %5, %6, %7}, {%8, %9}, {%0, %1, %2, %3};"
        : "+f"(c[0]), "+f"(c[1]), "+f"(c[2]), "+f"(c[3])
        : "r"(a[0]), "r"(a[1]), "r"(a[2]), "r"(a[3]), "r"(b[0]), "r"(b[1]));
}
__device__ __forceinline__ void cp_async16(uint32_t smem_dst, const void* gsrc) {
    asm volatile("cp.async.cg.shared.global [%0], [%1], 16;"
                 :: "r"(smem_dst), "l"(gsrc) : "memory");
}
#define CP_COMMIT() asm volatile("cp.async.commit_group;" ::: "memory")
#define CP_WAIT0()  asm volatile("cp.async.wait_group 0;" ::: "memory")

// ============================================================================
// Kernel 0: convert W -> bf16 hi/lo in chunk-major layout [kc][n][kk]
// ============================================================================
__global__ void wconv_kernel(const float* __restrict__ w,
                             __nv_bfloat16* __restrict__ wh,
                             __nv_bfloat16* __restrict__ wl)
{
    int idx = blockIdx.x * blockDim.x + threadIdx.x;
    if (idx >= INDIM * OUTDIM) return;
    int kc = idx >> 13;
    int n  = (idx >> 6) & 127;
    int kk = idx & 63;
    float f = w[(size_t)(kc * 64 + kk) * OUTDIM + n];
    __nv_bfloat16 h = __float2bfloat16(f);
    wh[idx] = h;
    wl[idx] = __float2bfloat16(f - __bfloat162float(h));
}

// ============================================================================
// CSR build
// ============================================================================
__global__ void zero_deg_kernel(int* __restrict__ deg, int n)
{
    int i = blockIdx.x * blockDim.x + threadIdx.x;
    if (i < n) deg[i] = 0;
}

__global__ void hist_kernel(const int* __restrict__ esrc, int* __restrict__ deg, int E)
{
    int i = blockIdx.x * blockDim.x + threadIdx.x;
    if (i < E) atomicAdd(&deg[esrc[i]], 1);
}

__global__ __launch_bounds__(SCAN_BLK) void scan_a_kernel(
    const int* __restrict__ deg, int* __restrict__ rowtmp, int* __restrict__ bsum, int n)
{
    __shared__ int s[SCAN_BLK];
    int gi = blockIdx.x * SCAN_BLK + threadIdx.x;
    int v = (gi < n) ? deg[gi] : 0;
    s[threadIdx.x] = v;
    __syncthreads();
#pragma unroll
    for (int off = 1; off < SCAN_BLK; off <<= 1) {
        int add = (threadIdx.x >= off) ? s[threadIdx.x - off] : 0;
        __syncthreads();
        s[threadIdx.x] += add;
        __syncthreads();
    }
    if (gi < n) rowtmp[gi] = s[threadIdx.x] - v;
    if (threadIdx.x == SCAN_BLK - 1) bsum[blockIdx.x] = s[threadIdx.x];
}

__global__ __launch_bounds__(128) void scan_b_kernel(int* __restrict__ bsum, int nb)
{
    __shared__ int s[128];
    int v = (threadIdx.x < nb) ? bsum[threadIdx.x] : 0;
    s[threadIdx.x] = v;
    __syncthreads();
#pragma unroll
    for (int off = 1; off < 128; off <<= 1) {
        int add = (threadIdx.x >= off) ? s[threadIdx.x - off] : 0;
        __syncthreads();
        s[threadIdx.x] += add;
        __syncthreads();
    }
    if (threadIdx.x < nb) bsum[threadIdx.x] = s[threadIdx.x] - v;
}

__global__ void scan_c_kernel(const int* __restrict__ rowtmp, const int* __restrict__ bsum,
                              int* __restrict__ rowstart, int* __restrict__ cursor, int n)
{
    int gi = blockIdx.x * SCAN_BLK + threadIdx.x;
    if (gi < n) {
        int v = rowtmp[gi] + bsum[blockIdx.x];
        rowstart[gi] = v;
        cursor[gi] = v;
    }
}

__global__ void reorder_kernel(const int* __restrict__ esrc, const int* __restrict__ edst,
                               const float* __restrict__ ev, int* __restrict__ cursor,
                               int2* __restrict__ edges, int E)
{
    int i = blockIdx.x * blockDim.x + threadIdx.x;
    if (i >= E) return;
    int s = esrc[i];
    int pos = atomicAdd(&cursor[s], 1);
    edges[pos] = make_int2(edst[i], __float_as_int(ev[i]));
}

// ============================================================================
// Gather: one warp per node. out[node] = bias + sum_e val_e * support[dst_e]
// ============================================================================
__global__ __launch_bounds__(256) void gather_kernel(
    const float* __restrict__ sup,
    const int* __restrict__ rowstart,
    const int* __restrict__ deg,
    const int2* __restrict__ edges,
    const float* __restrict__ bias,
    float* __restrict__ out,
    int N)
{
    int node = (blockIdx.x * blockDim.x + threadIdx.x) >> 5;
    int lane = threadIdx.x & 31;
    if (node >= N) return;

    int start = rowstart[node];
    int d = deg[node];

    float4 acc = reinterpret_cast<const float4*>(bias)[lane];

    for (int c = 0; c < d; c += 32) {
        int nchunk = min(32, d - c);
        int2 p = (lane < nchunk) ? edges[start + c + lane] : make_int2(0, 0);
        for (int j = 0; j < nchunk; j++) {
            int dn  = __shfl_sync(0xFFFFFFFFu, p.x, j);
            float v = __int_as_float(__shfl_sync(0xFFFFFFFFu, p.y, j));
            float4 a = reinterpret_cast<const float4*>(sup + (size_t)dn * OUTDIM)[lane];
            acc.x = fmaf(v, a.x, acc.x);
            acc.y = fmaf(v, a.y, acc.y);
            acc.z = fmaf(v, a.z, acc.z);
            acc.w = fmaf(v, a.w, acc.w);
        }
    }
    reinterpret_cast<float4*>(out + (size_t)node * OUTDIM)[lane] = acc;
}

// ============================================================================
// GEMM: bf16 split-precision HMMA, pipelined (unchanged R6 winner).
// ============================================================================
#define SM_BHI  0
#define SM_BLO  65536
#define SM_ABUF 131072
#define SM_GEMM_TOTAL 196608

__global__ __launch_bounds__(256) void gemm_mma_kernel(
    const float* __restrict__ x,
    const __nv_bfloat16* __restrict__ wh,
    const __nv_bfloat16* __restrict__ wl,
    float* __restrict__ sup,
    int M)
{
    extern __shared__ char smem[];
    const uint32_t sbase = smem_u32(smem);
    const int tid = threadIdx.x;
    const int wid = tid >> 5;
    const int lane = tid & 31;
    const int block_row = blockIdx.x * 128;

    const int m_off = (wid & 3) * 32;
    const int n_off = (wid >> 2) * 64;

    {
        const char* whb = reinterpret_cast<const char*>(wh);
        const char* wlb = reinterpret_cast<const char*>(wl);
#pragma unroll
        for (int i = 0; i < 32; i++) {
            int p = tid + i * 256;
            int kc = p >> 10;
            int within = (p & 1023) * 16;
            uint32_t dst = SW128((uint32_t)within) + kc * 16384;
            cp_async16(sbase + SM_BHI + dst, whb + (size_t)p * 16);
            cp_async16(sbase + SM_BLO + dst, wlb + (size_t)p * 16);
        }
        CP_COMMIT();
    }

    const int ar = tid >> 1;
    const int ahalf = tid & 1;
    const int agrow = block_row + ar;
    const float4* asrc_base = reinterpret_cast<const float4*>(
        x + (size_t)agrow * INDIM + ahalf * 32);

    float4 a4[8];
#pragma unroll
    for (int q = 0; q < 8; q++)
        a4[q] = (agrow < M) ? asrc_base[q] : make_float4(0.f, 0.f, 0.f, 0.f);

    auto convert_sts = [&](int buf) {
        uint32_t hibase = (uint32_t)SM_ABUF + (uint32_t)buf * 32768;
#pragma unroll
        for (int q = 0; q < 8; q++) {
            float4 f = a4[q];
            int c0 = ahalf * 32 + q * 4;
            __nv_bfloat16 hx = __float2bfloat16(f.x);
            __nv_bfloat16 hy = __float2bfloat16(f.y);
            __nv_bfloat16 hz = __float2bfloat16(f.z);
            __nv_bfloat16 hw = __float2bfloat16(f.w);
            __nv_bfloat162 ph0 = __nv_bfloat162(hx, hy);
            __nv_bfloat162 ph1 = __nv_bfloat162(hz, hw);
            __nv_bfloat162 pl0 = __nv_bfloat162(
                __float2bfloat16(f.x - __bfloat162float(hx)),
                __float2bfloat16(f.y - __bfloat162float(hy)));
            __nv_bfloat162 pl1 = __nv_bfloat162(
                __float2bfloat16(f.z - __bfloat162float(hz)),
                __float2bfloat16(f.w - __bfloat162float(hw)));
            uint32_t boff = (uint32_t)ar * 128 + (uint32_t)c0 * 2;
            uint32_t sw0 = SW128(boff);
            uint32_t sw1 = SW128(boff + 4);
            *reinterpret_cast<__nv_bfloat162*>(smem + hibase + sw0) = ph0;
            *reinterpret_cast<__nv_bfloat162*>(smem + hibase + sw1) = ph1;
            *reinterpret_cast<__nv_bfloat162*>(smem + hibase + 16384 + sw0) = pl0;
            *reinterpret_cast<__nv_bfloat162*>(smem + hibase + 16384 + sw1) = pl1;
        }
    };

    convert_sts(0);
    CP_WAIT0();
    __syncthreads();

    float acc[2][8][4];
#pragma unroll
    for (int mt = 0; mt < 2; mt++)
#pragma unroll
        for (int nt = 0; nt < 8; nt++)
#pragma unroll
            for (int q = 0; q < 4; q++) acc[mt][nt][q] = 0.0f;

    const int lrow = lane & 15;
    const int lkh = (lane >> 4) * 8;

    for (int kc = 0; kc < 4; kc++) {
        if (kc < 3) {
#pragma unroll
            for (int q = 0; q < 8; q++)
                a4[q] = (agrow < M) ? asrc_base[(kc + 1) * 16 + q]
                                    : make_float4(0.f, 0.f, 0.f, 0.f);
        }

        const uint32_t abuf_hi = sbase + SM_ABUF + (uint32_t)(kc & 1) * 32768;
        const uint32_t bchunk = (uint32_t)kc * 16384;

#pragma unroll
        for (int ks = 0; ks < 4; ks++) {
            const int k_off = ks * 16;
            uint32_t a_addr[2], b_addr[4];
#pragma unroll
            for (int mt = 0; mt < 2; mt++) {
                uint32_t boff = (uint32_t)(m_off + mt * 16 + lrow) * 128 +
                                (uint32_t)(k_off + lkh) * 2;
                a_addr[mt] = abuf_hi + SW128(boff);
            }
#pragma unroll
            for (int np = 0; np < 4; np++) {
                uint32_t boff = (uint32_t)(n_off + np * 16 + lrow) * 128 +
                                (uint32_t)(k_off + lkh) * 2;
                b_addr[np] = sbase + bchunk + SW128(boff);
            }

            uint32_t a_hi[2][4], a_lo[2][4], b[4][4];

#pragma unroll
            for (int np = 0; np < 4; np++)
                ldsm_x4(b[np][0], b[np][1], b[np][2], b[np][3], b_addr[np] + SM_BHI);
#pragma unroll
            for (int mt = 0; mt < 2; mt++)
                ldsm_x4(a_hi[mt][0], a_hi[mt][1], a_hi[mt][2], a_hi[mt][3], a_addr[mt]);
#pragma unroll
            for (int mt = 0; mt < 2; mt++)
#pragma unroll
                for (int np = 0; np < 4; np++) {
                    uint32_t b0[2] = { b[np][0], b[np][2] };
                    uint32_t b1[2] = { b[np][1], b[np][3] };
                    mma_bf16(acc[mt][2 * np + 0], a_hi[mt], b0);
                    mma_bf16(acc[mt][2 * np + 1], a_hi[mt], b1);
                }
#pragma unroll
            for (int mt = 0; mt < 2; mt++)
                ldsm_x4(a_lo[mt][0], a_lo[mt][1], a_lo[mt][2], a_lo[mt][3],
                        a_addr[mt] + 16384);
#pragma unroll
            for (int mt = 0; mt < 2; mt++)
#pragma unroll
                for (int np = 0; np < 4; np++) {
                    uint32_t b0[2] = { b[np][0], b[np][2] };
                    uint32_t b1[2] = { b[np][1], b[np][3] };
                    mma_bf16(acc[mt][2 * np + 0], a_lo[mt], b0);
                    mma_bf16(acc[mt][2 * np + 1], a_lo[mt], b1);
                }
#pragma unroll
            for (int np = 0; np < 4; np++)
                ldsm_x4(b[np][0], b[np][1], b[np][2], b[np][3], b_addr[np] + SM_BLO);
#pragma unroll
            for (int mt = 0; mt < 2; mt++)
#pragma unroll
                for (int np = 0; np < 4; np++) {
                    uint32_t b0[2] = { b[np][0], b[np][2] };
                    uint32_t b1[2] = { b[np][1], b[np][3] };
                    mma_bf16(acc[mt][2 * np + 0], a_hi[mt], b0);
                    mma_bf16(acc[mt][2 * np + 1], a_hi[mt], b1);
                }
        }

        if (kc < 3) {
            convert_sts((kc + 1) & 1);
            __syncthreads();
        }
    }

    const int rbase = block_row + m_off + (lane >> 2);
    const int cbase = n_off + 2 * (lane & 3);
#pragma unroll
    for (int mt = 0; mt < 2; mt++) {
        int r0 = rbase + mt * 16;
        int r1 = r0 + 8;
        if (r0 < M) {
            float* d0 = sup + (size_t)r0 * OUTDIM + cbase;
#pragma unroll
            for (int nt = 0; nt < 8; nt++)
                *reinterpret_cast<float2*>(d0 + nt * 8) =
                    make_float2(acc[mt][nt][0], acc[mt][nt][1]);
        }
        if (r1 < M) {
            float* d1 = sup + (size_t)r1 * OUTDIM + cbase;
#pragma unroll
            for (int nt = 0; nt < 8; nt++)
                *reinterpret_cast<float2*>(d1 + nt * 8) =
                    make_float2(acc[mt][nt][2], acc[mt][nt][3]);
        }
    }
}

// ---------------------------------------------------------------------------
extern "C" void kernel_launch(void* const* d_in, const int* in_sizes, int n_in,
                              void* d_out, int out_size)
{
    const float* x    = (const float*)d_in[0];
    const float* w    = (const float*)d_in[1];
    const float* bias = (const float*)d_in[2];
    const int*   esrc = (const int*)d_in[3];
    const int*   edst = (const int*)d_in[4];
    const float* ev   = (const float*)d_in[5];
    float* out = (float*)d_out;

    const int M = in_sizes[0] / INDIM;   // 100000
    const int E = in_sizes[3];           // 1600000

    float* sup;        cudaGetSymbolAddress((void**)&sup, g_support);
    __nv_bfloat16* wh; cudaGetSymbolAddress((void**)&wh, g_wh);
    __nv_bfloat16* wl; cudaGetSymbolAddress((void**)&wl, g_wl);
    int* deg;          cudaGetSymbolAddress((void**)&deg, g_deg);
    int* rowtmp;       cudaGetSymbolAddress((void**)&rowtmp, g_rowtmp);
    int* rowstart;     cudaGetSymbolAddress((void**)&rowstart, g_rowstart);
    int* cursor;       cudaGetSymbolAddress((void**)&cursor, g_cursor);
    int* bsum;         cudaGetSymbolAddress((void**)&bsum, g_bsum);
    int2* edges;       cudaGetSymbolAddress((void**)&edges, g_edges);

    cudaFuncSetAttribute(gemm_mma_kernel,
                         cudaFuncAttributeMaxDynamicSharedMemorySize, SM_GEMM_TOTAL);

    // One-time resources for the parallel branch (created on first, uncaptured
    // call; reused identically on every subsequent call).
    static cudaStream_t s2 = nullptr;
    static cudaEvent_t evFork = nullptr, evJoin = nullptr;
    if (s2 == nullptr) {
        cudaStreamCreateWithFlags(&s2, cudaStreamNonBlocking);
        cudaEventCreateWithFlags(&evFork, cudaEventDisableTiming);
        cudaEventCreateWithFlags(&evJoin, cudaEventDisableTiming);
    }

    // --- Fork: CSR build on s2, concurrent with wconv+GEMM on main stream ---
    cudaEventRecord(evFork, 0);
    cudaStreamWaitEvent(s2, evFork, 0);

    zero_deg_kernel<<<(M + 255) / 256, 256, 0, s2>>>(deg, M);
    hist_kernel<<<(E + 255) / 256, 256, 0, s2>>>(esrc, deg, E);
    int nsb = (M + SCAN_BLK - 1) / SCAN_BLK;
    scan_a_kernel<<<nsb, SCAN_BLK, 0, s2>>>(deg, rowtmp, bsum, M);
    scan_b_kernel<<<1, 128, 0, s2>>>(bsum, nsb);
    scan_c_kernel<<<nsb, SCAN_BLK, 0, s2>>>(rowtmp, bsum, rowstart, cursor, M);
    reorder_kernel<<<(E + 255) / 256, 256, 0, s2>>>(esrc, edst, ev, cursor, edges, E);
    cudaEventRecord(evJoin, s2);

    // --- Main stream: W convert + GEMM ---
    wconv_kernel<<<(INDIM * OUTDIM + 255) / 256, 256>>>(w, wh, wl);
    int gblocks = (M + 127) / 128;
    gemm_mma_kernel<<<gblocks, 256, SM_GEMM_TOTAL>>>(x, wh, wl, sup, M);

    // --- Join, then gather ---
    cudaStreamWaitEvent(0, evJoin, 0);
    int gth_blocks = (M * 32 + 255) / 256;
    gather_kernel<<<gth_blocks, 256>>>(sup, rowstart, deg, edges, bias, out, M);
}

// round 10
// speedup vs baseline: 3.1642x; 1.0365x over previous
#include <cuda_runtime.h>
#include <cuda_bf16.h>
#include <cstdint>

#define NNODES 100000
#define INDIM  256
#define OUTDIM 128
#define NEDGES_MAX 1700000
#define SCAN_BLK 1024

// Scratch
__device__ float g_support[(size_t)NNODES * OUTDIM];                 // 51.2 MB (fp32)
__device__ __align__(16) __nv_bfloat16 g_wh[INDIM * OUTDIM];
__device__ __align__(16) __nv_bfloat16 g_wl[INDIM * OUTDIM];
__device__ int  g_deg[NNODES];
__device__ int  g_rowtmp[NNODES];
__device__ int  g_rowstart[NNODES];
__device__ int  g_cursor[NNODES];
__device__ int  g_bsum[128];
__device__ int2 g_edges[NEDGES_MAX];                                 // {dst, val bits}

// ============================================================================
// Helpers
// ============================================================================
__device__ __forceinline__ uint32_t smem_u32(const void* p) {
    uint32_t a;
    asm("{ .reg .u64 t; cvta.to.shared.u64 t, %1; cvt.u32.u64 %0, t; }" : "=r"(a) : "l"(p));
    return a;
}
#define SW128(off) ((off) ^ (((off) >> 3) & 0x70))

__device__ __forceinline__ void ldsm_x4(uint32_t& r0, uint32_t& r1, uint32_t& r2, uint32_t& r3,
                                        uint32_t addr) {
    asm volatile("ldmatrix.sync.aligned.m8n8.x4.shared.b16 {%0, %1, %2, %3}, [%4];"
                 : "=r"(r0), "=r"(r1), "=r"(r2), "=r"(r3) : "r"(addr));
}
__device__ __forceinline__ void mma_bf16(float* c, const uint32_t* a, const uint32_t* b) {
    asm volatile(
        "mma.sync.aligned.m16n8k16.row.col.f32.bf16.bf16.f32 "
        "{%0, %1, %2, %3}, {%4, %5, %6, %7}, {%8, %9}, {%0, %1, %2, %3};"
        : "+f"(c[0]), "+f"(c[1]), "+f"(c[2]), "+f"(c[3])
        : "r"(a[0]), "r"(a[1]), "r"(a[2]), "r"(a[3]), "r"(b[0]), "r"(b[1]));
}
__device__ __forceinline__ void cp_async16(uint32_t smem_dst, const void* gsrc) {
    asm volatile("cp.async.cg.shared.global [%0], [%1], 16;"
                 :: "r"(smem_dst), "l"(gsrc) : "memory");
}
#define CP_COMMIT() asm volatile("cp.async.commit_group;" ::: "memory")
#define CP_WAIT0()  asm volatile("cp.async.wait_group 0;" ::: "memory")

// ============================================================================
// Kernel 0: convert W -> bf16 hi/lo in chunk-major layout [kc][n][kk]
// ============================================================================
__global__ void wconv_kernel(const float* __restrict__ w,
                             __nv_bfloat16* __restrict__ wh,
                             __nv_bfloat16* __restrict__ wl)
{
    int idx = blockIdx.x * blockDim.x + threadIdx.x;
    if (idx >= INDIM * OUTDIM) return;
    int kc = idx >> 13;
    int n  = (idx >> 6) & 127;
    int kk = idx & 63;
    float f = w[(size_t)(kc * 64 + kk) * OUTDIM + n];
    __nv_bfloat16 h = __float2bfloat16(f);
    wh[idx] = h;
    wl[idx] = __float2bfloat16(f - __bfloat162float(h));
}

// ============================================================================
// CSR build
// ============================================================================
__global__ void zero_deg_kernel(int* __restrict__ deg, int n)
{
    int i = blockIdx.x * blockDim.x + threadIdx.x;
    if (i < n) deg[i] = 0;
}

__global__ void hist_kernel(const int* __restrict__ esrc, int* __restrict__ deg, int E)
{
    int i = blockIdx.x * blockDim.x + threadIdx.x;
    if (i < E) atomicAdd(&deg[esrc[i]], 1);
}

__global__ __launch_bounds__(SCAN_BLK) void scan_a_kernel(
    const int* __restrict__ deg, int* __restrict__ rowtmp, int* __restrict__ bsum, int n)
{
    __shared__ int s[SCAN_BLK];
    int gi = blockIdx.x * SCAN_BLK + threadIdx.x;
    int v = (gi < n) ? deg[gi] : 0;
    s[threadIdx.x] = v;
    __syncthreads();
#pragma unroll
    for (int off = 1; off < SCAN_BLK; off <<= 1) {
        int add = (threadIdx.x >= off) ? s[threadIdx.x - off] : 0;
        __syncthreads();
        s[threadIdx.x] += add;
        __syncthreads();
    }
    if (gi < n) rowtmp[gi] = s[threadIdx.x] - v;
    if (threadIdx.x == SCAN_BLK - 1) bsum[blockIdx.x] = s[threadIdx.x];
}

__global__ __launch_bounds__(128) void scan_b_kernel(int* __restrict__ bsum, int nb)
{
    __shared__ int s[128];
    int v = (threadIdx.x < nb) ? bsum[threadIdx.x] : 0;
    s[threadIdx.x] = v;
    __syncthreads();
#pragma unroll
    for (int off = 1; off < 128; off <<= 1) {
        int add = (threadIdx.x >= off) ? s[threadIdx.x - off] : 0;
        __syncthreads();
        s[threadIdx.x] += add;
        __syncthreads();
    }
    if (threadIdx.x < nb) bsum[threadIdx.x] = s[threadIdx.x] - v;
}

__global__ void scan_c_kernel(const int* __restrict__ rowtmp, const int* __restrict__ bsum,
                              int* __restrict__ rowstart, int* __restrict__ cursor, int n)
{
    int gi = blockIdx.x * SCAN_BLK + threadIdx.x;
    if (gi < n) {
        int v = rowtmp[gi] + bsum[blockIdx.x];
        rowstart[gi] = v;
        cursor[gi] = v;
    }
}

__global__ void reorder_kernel(const int* __restrict__ esrc, const int* __restrict__ edst,
                               const float* __restrict__ ev, int* __restrict__ cursor,
                               int2* __restrict__ edges, int E)
{
    int i = blockIdx.x * blockDim.x + threadIdx.x;
    if (i >= E) return;
    int s = esrc[i];
    int pos = atomicAdd(&cursor[s], 1);
    edges[pos] = make_int2(edst[i], __float_as_int(ev[i]));
}

// ============================================================================
// Gather: one warp per node. out[node] = bias + sum_e val_e * support[dst_e]
// (identical to the 213us-passing version)
// ============================================================================
__global__ __launch_bounds__(256) void gather_kernel(
    const float* __restrict__ sup,
    const int* __restrict__ rowstart,
    const int* __restrict__ deg,
    const int2* __restrict__ edges,
    const float* __restrict__ bias,
    float* __restrict__ out,
    int N)
{
    int node = (blockIdx.x * blockDim.x + threadIdx.x) >> 5;
    int lane = threadIdx.x & 31;
    if (node >= N) return;

    int start = rowstart[node];
    int d = deg[node];

    float4 acc = reinterpret_cast<const float4*>(bias)[lane];

    for (int c = 0; c < d; c += 32) {
        int nchunk = min(32, d - c);
        int2 p = (lane < nchunk) ? edges[start + c + lane] : make_int2(0, 0);
        for (int j = 0; j < nchunk; j++) {
            int dn  = __shfl_sync(0xFFFFFFFFu, p.x, j);
            float v = __int_as_float(__shfl_sync(0xFFFFFFFFu, p.y, j));
            float4 a = reinterpret_cast<const float4*>(sup + (size_t)dn * OUTDIM)[lane];
            acc.x = fmaf(v, a.x, acc.x);
            acc.y = fmaf(v, a.y, acc.y);
            acc.z = fmaf(v, a.z, acc.z);
            acc.w = fmaf(v, a.w, acc.w);
        }
    }
    reinterpret_cast<float4*>(out + (size_t)node * OUTDIM)[lane] = acc;
}

// ============================================================================
// GEMM: bf16 split-precision HMMA, pipelined. 256 threads, warp tile 32x64
// (the PROVEN R7 configuration), with two additions:
//  - M-tile 256 per CTA: run the 128-row pipeline twice, reusing resident B.
//  - fragment widening: all ldsm up front, separate b_lo regs, 72 MMAs ILP.
// ============================================================================
#define SM_BHI  0
#define SM_BLO  65536
#define SM_ABUF 131072
#define SM_GEMM_TOTAL 196608

__global__ __launch_bounds__(256) void gemm_mma_kernel(
    const float* __restrict__ x,
    const __nv_bfloat16* __restrict__ wh,
    const __nv_bfloat16* __restrict__ wl,
    float* __restrict__ sup,
    int M)
{
    extern __shared__ char smem[];
    const uint32_t sbase = smem_u32(smem);
    const int tid = threadIdx.x;
    const int wid = tid >> 5;
    const int lane = tid & 31;

    const int m_off = (wid & 3) * 32;
    const int n_off = (wid >> 2) * 64;

    // ---- B cp.async once per CTA (128KB) ----
    {
        const char* whb = reinterpret_cast<const char*>(wh);
        const char* wlb = reinterpret_cast<const char*>(wl);
#pragma unroll
        for (int i = 0; i < 32; i++) {
            int p = tid + i * 256;
            int kc = p >> 10;
            int within = (p & 1023) * 16;
            uint32_t dst = SW128((uint32_t)within) + kc * 16384;
            cp_async16(sbase + SM_BHI + dst, whb + (size_t)p * 16);
            cp_async16(sbase + SM_BLO + dst, wlb + (size_t)p * 16);
        }
        CP_COMMIT();
    }

    const int ar = tid >> 1;
    const int ahalf = tid & 1;
    const int lrow = lane & 15;
    const int lkh = (lane >> 4) * 8;

    for (int mhalf = 0; mhalf < 2; mhalf++) {
        const int block_row = blockIdx.x * 256 + mhalf * 128;
        const int agrow = block_row + ar;
        const float4* asrc_base = reinterpret_cast<const float4*>(
            x + (size_t)agrow * INDIM + ahalf * 32);

        float4 a4[8];
#pragma unroll
        for (int q = 0; q < 8; q++)
            a4[q] = (agrow < M) ? asrc_base[q] : make_float4(0.f, 0.f, 0.f, 0.f);

        auto convert_sts = [&](int buf) {
            uint32_t hibase = (uint32_t)SM_ABUF + (uint32_t)buf * 32768;
#pragma unroll
            for (int q = 0; q < 8; q++) {
                float4 f = a4[q];
                int c0 = ahalf * 32 + q * 4;
                __nv_bfloat16 hx = __float2bfloat16(f.x);
                __nv_bfloat16 hy = __float2bfloat16(f.y);
                __nv_bfloat16 hz = __float2bfloat16(f.z);
                __nv_bfloat16 hw = __float2bfloat16(f.w);
                __nv_bfloat162 ph0 = __nv_bfloat162(hx, hy);
                __nv_bfloat162 ph1 = __nv_bfloat162(hz, hw);
                __nv_bfloat162 pl0 = __nv_bfloat162(
                    __float2bfloat16(f.x - __bfloat162float(hx)),
                    __float2bfloat16(f.y - __bfloat162float(hy)));
                __nv_bfloat162 pl1 = __nv_bfloat162(
                    __float2bfloat16(f.z - __bfloat162float(hz)),
                    __float2bfloat16(f.w - __bfloat162float(hw)));
                uint32_t boff = (uint32_t)ar * 128 + (uint32_t)c0 * 2;
                uint32_t sw0 = SW128(boff);
                uint32_t sw1 = SW128(boff + 4);
                *reinterpret_cast<__nv_bfloat162*>(smem + hibase + sw0) = ph0;
                *reinterpret_cast<__nv_bfloat162*>(smem + hibase + sw1) = ph1;
                *reinterpret_cast<__nv_bfloat162*>(smem + hibase + 16384 + sw0) = pl0;
                *reinterpret_cast<__nv_bfloat162*>(smem + hibase + 16384 + sw1) = pl1;
            }
        };

        convert_sts(0);
        if (mhalf == 0) CP_WAIT0();
        __syncthreads();   // buf0 (+ B on first half) visible to all warps

        float acc[2][8][4];
#pragma unroll
        for (int mt = 0; mt < 2; mt++)
#pragma unroll
            for (int nt = 0; nt < 8; nt++)
#pragma unroll
                for (int q = 0; q < 4; q++) acc[mt][nt][q] = 0.0f;

        for (int kc = 0; kc < 4; kc++) {
            if (kc < 3) {
#pragma unroll
                for (int q = 0; q < 8; q++)
                    a4[q] = (agrow < M) ? asrc_base[(kc + 1) * 16 + q]
                                        : make_float4(0.f, 0.f, 0.f, 0.f);
            }

            const uint32_t abuf_hi = sbase + SM_ABUF + (uint32_t)(kc & 1) * 32768;
            const uint32_t bchunk = (uint32_t)kc * 16384;

#pragma unroll
            for (int ks = 0; ks < 4; ks++) {
                const int k_off = ks * 16;
                uint32_t a_addr[2], b_addr[4];
#pragma unroll
                for (int mt = 0; mt < 2; mt++) {
                    uint32_t boff = (uint32_t)(m_off + mt * 16 + lrow) * 128 +
                                    (uint32_t)(k_off + lkh) * 2;
                    a_addr[mt] = abuf_hi + SW128(boff);
                }
#pragma unroll
                for (int np = 0; np < 4; np++) {
                    uint32_t boff = (uint32_t)(n_off + np * 16 + lrow) * 128 +
                                    (uint32_t)(k_off + lkh) * 2;
                    b_addr[np] = sbase + bchunk + SW128(boff);
                }

                // Load ALL fragments first (wide registers, full ILP)
                uint32_t a_hi[2][4], a_lo[2][4], bh[4][4], bl[4][4];
#pragma unroll
                for (int np = 0; np < 4; np++)
                    ldsm_x4(bh[np][0], bh[np][1], bh[np][2], bh[np][3],
                            b_addr[np] + SM_BHI);
#pragma unroll
                for (int np = 0; np < 4; np++)
                    ldsm_x4(bl[np][0], bl[np][1], bl[np][2], bl[np][3],
                            b_addr[np] + SM_BLO);
#pragma unroll
                for (int mt = 0; mt < 2; mt++)
                    ldsm_x4(a_hi[mt][0], a_hi[mt][1], a_hi[mt][2], a_hi[mt][3],
                            a_addr[mt]);
#pragma unroll
                for (int mt = 0; mt < 2; mt++)
                    ldsm_x4(a_lo[mt][0], a_lo[mt][1], a_lo[mt][2], a_lo[mt][3],
                            a_addr[mt] + 16384);

                // 72 MMAs, three precision terms interleaved per (mt, np)
#pragma unroll
                for (int mt = 0; mt < 2; mt++)
#pragma unroll
                    for (int np = 0; np < 4; np++) {
                        uint32_t bh0[2] = { bh[np][0], bh[np][2] };
                        uint32_t bh1[2] = { bh[np][1], bh[np][3] };
                        uint32_t bl0[2] = { bl[np][0], bl[np][2] };
                        uint32_t bl1[2] = { bl[np][1], bl[np][3] };
                        mma_bf16(acc[mt][2 * np + 0], a_hi[mt], bh0);
                        mma_bf16(acc[mt][2 * np + 1], a_hi[mt], bh1);
                        mma_bf16(acc[mt][2 * np + 0], a_lo[mt], bh0);
                        mma_bf16(acc[mt][2 * np + 1], a_lo[mt], bh1);
                        mma_bf16(acc[mt][2 * np + 0], a_hi[mt], bl0);
                        mma_bf16(acc[mt][2 * np + 1], a_hi[mt], bl1);
                    }
            }

            if (kc < 3) {
                convert_sts((kc + 1) & 1);
                __syncthreads();
            }
        }

        // ---- Epilogue for this m-half (fp32 output) ----
        const int rbase = block_row + m_off + (lane >> 2);
        const int cbase = n_off + 2 * (lane & 3);
#pragma unroll
        for (int mt = 0; mt < 2; mt++) {
            int r0 = rbase + mt * 16;
            int r1 = r0 + 8;
            if (r0 < M) {
                float* d0 = sup + (size_t)r0 * OUTDIM + cbase;
#pragma unroll
                for (int nt = 0; nt < 8; nt++)
                    *reinterpret_cast<float2*>(d0 + nt * 8) =
                        make_float2(acc[mt][nt][0], acc[mt][nt][1]);
            }
            if (r1 < M) {
                float* d1 = sup + (size_t)r1 * OUTDIM + cbase;
#pragma unroll
                for (int nt = 0; nt < 8; nt++)
                    *reinterpret_cast<float2*>(d1 + nt * 8) =
                        make_float2(acc[mt][nt][2], acc[mt][nt][3]);
            }
        }
    }
}

// ---------------------------------------------------------------------------
extern "C" void kernel_launch(void* const* d_in, const int* in_sizes, int n_in,
                              void* d_out, int out_size)
{
    const float* x    = (const float*)d_in[0];
    const float* w    = (const float*)d_in[1];
    const float* bias = (const float*)d_in[2];
    const int*   esrc = (const int*)d_in[3];
    const int*   edst = (const int*)d_in[4];
    const float* ev   = (const float*)d_in[5];
    float* out = (float*)d_out;

    const int M = in_sizes[0] / INDIM;   // 100000
    const int E = in_sizes[3];           // 1600000

    float* sup;        cudaGetSymbolAddress((void**)&sup, g_support);
    __nv_bfloat16* wh; cudaGetSymbolAddress((void**)&wh, g_wh);
    __nv_bfloat16* wl; cudaGetSymbolAddress((void**)&wl, g_wl);
    int* deg;          cudaGetSymbolAddress((void**)&deg, g_deg);
    int* rowtmp;       cudaGetSymbolAddress((void**)&rowtmp, g_rowtmp);
    int* rowstart;     cudaGetSymbolAddress((void**)&rowstart, g_rowstart);
    int* cursor;       cudaGetSymbolAddress((void**)&cursor, g_cursor);
    int* bsum;         cudaGetSymbolAddress((void**)&bsum, g_bsum);
    int2* edges;       cudaGetSymbolAddress((void**)&edges, g_edges);

    cudaFuncSetAttribute(gemm_mma_kernel,
                         cudaFuncAttributeMaxDynamicSharedMemorySize, SM_GEMM_TOTAL);

    static cudaStream_t s2 = nullptr;
    static cudaEvent_t evFork = nullptr, evJoin = nullptr;
    if (s2 == nullptr) {
        cudaStreamCreateWithFlags(&s2, cudaStreamNonBlocking);
        cudaEventCreateWithFlags(&evFork, cudaEventDisableTiming);
        cudaEventCreateWithFlags(&evJoin, cudaEventDisableTiming);
    }

    // --- Fork: CSR build on s2, concurrent with wconv+GEMM ---
    cudaEventRecord(evFork, 0);
    cudaStreamWaitEvent(s2, evFork, 0);

    zero_deg_kernel<<<(M + 255) / 256, 256, 0, s2>>>(deg, M);
    hist_kernel<<<(E + 255) / 256, 256, 0, s2>>>(esrc, deg, E);
    int nsb = (M + SCAN_BLK - 1) / SCAN_BLK;
    scan_a_kernel<<<nsb, SCAN_BLK, 0, s2>>>(deg, rowtmp, bsum, M);
    scan_b_kernel<<<1, 128, 0, s2>>>(bsum, nsb);
    scan_c_kernel<<<nsb, SCAN_BLK, 0, s2>>>(rowtmp, bsum, rowstart, cursor, M);
    reorder_kernel<<<(E + 255) / 256, 256, 0, s2>>>(esrc, edst, ev, cursor, edges, E);
    cudaEventRecord(evJoin, s2);

    // --- Main stream: W convert + GEMM (M-tile 256 per CTA) ---
    wconv_kernel<<<(INDIM * OUTDIM + 255) / 256, 256>>>(w, wh, wl);
    int gblocks = (M + 255) / 256;
    gemm_mma_kernel<<<gblocks, 256, SM_GEMM_TOTAL>>>(x, wh, wl, sup, M);

    // --- Join, then gather ---
    cudaStreamWaitEvent(0, evJoin, 0);
    int gth_blocks = (M * 32 + 255) / 256;
    gather_kernel<<<gth_blocks, 256>>>(sup, rowstart, deg, edges, bias, out, M);
}